// round 10
// baseline (speedup 1.0000x reference)
#include <cuda_runtime.h>
#include <cuda_bf16.h>
#include <cstdint>

#define N_NODES 400000
#define N_EDGES 1600000
#define HDIM 100
#define HDIM3 300
#define ADIM 50
#define CDIM 30
#define GTB 320          // threads for scalar tiled GEMM kernels
#define MTILE 128        // rows per sub-tile
#define NSUB 4           // sub-tiles per MMA CTA (512 rows)
#define SXS 132          // k-major tile row stride

// ---- mma.sync GRU-gi geometry ----
#define BW 17472                 // 56*312 words per B split
#define AW 7680                  // 128*60 words per A split
#define A_OFF (2*BW)             // A base word offset in gi smem
#define GI_SMEM ((2*BW + 2*AW) * 4)   // 201216 bytes

// ---- mma.sync MLP geometry ----
#define BW1 3136                 // 56*56 words per split
#define BW2 3328                 // 32*104 words per split
#define MB2_OFF (2*BW1)          // 6272
#define MSB_OFF (2*BW1 + 2*BW2)  // 12928 (biases, 160 words)
#define MA_OFF (MSB_OFF + 160)   // 13088
#define MLP_W (MA_OFF + 2*AW)    // 28448 words
#define MLP_SMEM (MLP_W * 4)     // 113792 bytes

typedef unsigned long long u64;

// ---------------- scratch (device globals) -------------------------------------
__device__ __align__(16) float g_h  [N_NODES * HDIM];
__device__ __align__(16) float g_h2 [N_NODES * HDIM];
__device__ __align__(16) float g_m  [N_NODES * HDIM];
__device__ __align__(16) float g_msg[N_NODES * HDIM];
__device__ __align__(16) float g_gi [(size_t)N_NODES * HDIM3];
__device__ __align__(16) uint32_t g_wbia[2][2 * BW];          // fwd/bwd wih images
__device__ __align__(16) uint32_t g_wmlp[2][MSB_OFF];          // fwd/bwd MLP images
__device__ int g_row[N_EDGES];
__device__ int g_col[N_EDGES];
__device__ int g_is64;
__device__ int g_degF[N_NODES];
__device__ int g_degB[N_NODES];
__device__ int g_rptrF[N_NODES + 1];
__device__ int g_rptrB[N_NODES + 1];
__device__ int g_curF[N_NODES];
__device__ int g_curB[N_NODES];
__device__ int g_csrF[N_EDGES];
__device__ int g_csrB[N_EDGES];
__device__ int g_incl[N_NODES];
__device__ int g_bsums[512];

// ---------------- helpers --------------------------------------------------------
__device__ __forceinline__ u64 pack2(float x, float y) {
    u64 r; asm("mov.b64 %0, {%1, %2};" : "=l"(r) : "f"(x), "f"(y)); return r;
}
__device__ __forceinline__ float2 unpack2(u64 v) {
    float2 r; asm("mov.b64 {%0, %1}, %2;" : "=f"(r.x), "=f"(r.y) : "l"(v)); return r;
}
__device__ __forceinline__ void fma2(u64& d, u64 a, u64 b) {
    asm("fma.rn.f32x2 %0, %1, %2, %0;" : "+l"(d) : "l"(a), "l"(b));
}
__device__ __forceinline__ float fsigmoid(float x) { return 1.0f / (1.0f + __expf(-x)); }
__device__ __forceinline__ float ftanh_(float x) {
    float e = __expf(2.0f * x);
    return 1.0f - 2.0f / (e + 1.0f);
}
__device__ __forceinline__ unsigned short bfu(float x) {
    __nv_bfloat16 b = __float2bfloat16(x);
    return *reinterpret_cast<unsigned short*>(&b);
}
__device__ __forceinline__ float bff(float x) {
    return __bfloat162float(__float2bfloat16(x));
}
__device__ __forceinline__ void mma_bf16(float c[4],
    uint32_t a0, uint32_t a1, uint32_t a2, uint32_t a3,
    uint32_t b0, uint32_t b1) {
    asm volatile(
        "mma.sync.aligned.m16n8k16.row.col.f32.bf16.bf16.f32 "
        "{%0,%1,%2,%3}, {%4,%5,%6,%7}, {%8,%9}, {%0,%1,%2,%3};"
        : "+f"(c[0]), "+f"(c[1]), "+f"(c[2]), "+f"(c[3])
        : "r"(a0), "r"(a1), "r"(a2), "r"(a3), "r"(b0), "r"(b1));
}

// ---------------- edge dtype detection & normalization -------------------------
__global__ void detect_kernel(const unsigned int* __restrict__ w) {
    unsigned int v = w[2 * threadIdx.x + 1];
    unsigned int any = __ballot_sync(0xffffffffu, v != 0u);
    if (threadIdx.x == 0) g_is64 = (any == 0u) ? 1 : 0;
}

__global__ void convert_kernel(const void* __restrict__ rp, const void* __restrict__ cp,
                               int* __restrict__ ro, int* __restrict__ co) {
    int e = blockIdx.x * blockDim.x + threadIdx.x;
    if (e >= N_EDGES) return;
    if (g_is64) {
        ro[e] = (int)((const long long*)rp)[e];
        co[e] = (int)((const long long*)cp)[e];
    } else {
        ro[e] = ((const int*)rp)[e];
        co[e] = ((const int*)cp)[e];
    }
}

// ---------------- CSR build ------------------------------------------------------
__global__ void deg_kernel(const int* __restrict__ row, const int* __restrict__ col,
                           int* __restrict__ degF, int* __restrict__ degB) {
    int e = blockIdx.x * blockDim.x + threadIdx.x;
    if (e >= N_EDGES) return;
    atomicAdd(&degF[row[e]], 1);
    atomicAdd(&degB[col[e]], 1);
}

__global__ void scan_block(const int* __restrict__ deg, int* __restrict__ incl,
                           int* __restrict__ bsums, int n) {
    __shared__ int s[1024];
    int i = blockIdx.x * 1024 + threadIdx.x;
    int v = (i < n) ? deg[i] : 0;
    s[threadIdx.x] = v;
    __syncthreads();
    #pragma unroll
    for (int off = 1; off < 1024; off <<= 1) {
        int t = (threadIdx.x >= off) ? s[threadIdx.x - off] : 0;
        __syncthreads();
        s[threadIdx.x] += t;
        __syncthreads();
    }
    if (i < n) incl[i] = s[threadIdx.x];
    if (threadIdx.x == 1023) bsums[blockIdx.x] = s[1023];
}

__global__ void scan_sums(int* __restrict__ bsums, int nb) {
    if (threadIdx.x == 0) {
        int acc = 0;
        for (int b = 0; b < nb; b++) { int t = bsums[b]; bsums[b] = acc; acc += t; }
    }
}

__global__ void scan_final(const int* __restrict__ incl, const int* __restrict__ deg,
                           const int* __restrict__ bsums, int* __restrict__ rptr, int n) {
    int i = blockIdx.x * 256 + threadIdx.x;
    if (i < n) rptr[i] = incl[i] - deg[i] + bsums[i >> 10];
    if (i == n) rptr[n] = N_EDGES;
}

__global__ void scatter_kernel(const int* __restrict__ row, const int* __restrict__ col,
                               int* __restrict__ curF, int* __restrict__ curB,
                               int* __restrict__ csrF, int* __restrict__ csrB) {
    int e = blockIdx.x * blockDim.x + threadIdx.x;
    if (e >= N_EDGES) return;
    int r = row[e], c = col[e];
    int pF = atomicAdd(&curF[r], 1);
    csrF[pF] = c;
    int pB = atomicAdd(&curB[c], 1);
    csrB[pB] = r;
}

// ---------------- weight prep (wih): image [kq(56)][n(312)] x 2 splits ----------
__global__ void prep_wb(const float* __restrict__ W, uint32_t* __restrict__ o) {
    int e = blockIdx.x * 256 + threadIdx.x;
    if (e >= BW) return;
    int kq = e / 312, n = e - kq * 312;
    int k0 = 2 * kq, k1 = k0 + 1;
    float w0 = (k0 < 100 && n < 300) ? W[k0 * 300 + n] : 0.0f;
    float w1 = (k1 < 100 && n < 300) ? W[k1 * 300 + n] : 0.0f;
    o[e] = (uint32_t)bfu(w0) | ((uint32_t)bfu(w1) << 16);
    float r0 = w0 - bff(w0), r1 = w1 - bff(w1);
    o[BW + e] = (uint32_t)bfu(r0) | ((uint32_t)bfu(r1) << 16);
}

// ---------------- weight prep (MLP): w1 [kq56][n56], w2 [kq32][n104] -------------
__global__ void prep_wmlp(const float* __restrict__ W1, const float* __restrict__ W2,
                          uint32_t* __restrict__ o) {
    int e = blockIdx.x * 256 + threadIdx.x;
    if (e < BW1) {
        int kq = e / 56, n = e - kq * 56;
        int k0 = 2 * kq, k1 = k0 + 1;
        float w0 = (k0 < 100 && n < 50) ? W1[k0 * 50 + n] : 0.0f;
        float w1 = (k1 < 100 && n < 50) ? W1[k1 * 50 + n] : 0.0f;
        o[e] = (uint32_t)bfu(w0) | ((uint32_t)bfu(w1) << 16);
        float r0 = w0 - bff(w0), r1 = w1 - bff(w1);
        o[BW1 + e] = (uint32_t)bfu(r0) | ((uint32_t)bfu(r1) << 16);
    } else if (e < BW1 + BW2) {
        int e2 = e - BW1;
        int kq = e2 / 104, n = e2 - kq * 104;
        int k0 = 2 * kq, k1 = k0 + 1;
        float w0 = (k0 < 50 && n < 100) ? W2[k0 * 100 + n] : 0.0f;
        float w1 = (k1 < 50 && n < 100) ? W2[k1 * 100 + n] : 0.0f;
        o[MB2_OFF + e2] = (uint32_t)bfu(w0) | ((uint32_t)bfu(w1) << 16);
        float r0 = w0 - bff(w0), r1 = w1 - bff(w1);
        o[MB2_OFF + BW2 + e2] = (uint32_t)bfu(r0) | ((uint32_t)bfu(r1) << 16);
    }
}

// ---------------- h0_T[d][n] = (features @ init_w + init_b)^T ------------------
__global__ void initT_kernel(const float* __restrict__ f, const float* __restrict__ w,
                             const float* __restrict__ b, float* __restrict__ hT) {
    __shared__ float sw[4 * HDIM];
    __shared__ float sb[HDIM];
    for (int i = threadIdx.x; i < 4 * HDIM; i += blockDim.x) sw[i] = w[i];
    for (int i = threadIdx.x; i < HDIM; i += blockDim.x) sb[i] = b[i];
    __syncthreads();
    int n = blockIdx.x * blockDim.x + threadIdx.x;
    float4 fv = *(const float4*)(f + (size_t)n * 4);
    #pragma unroll 4
    for (int d = 0; d < HDIM; d++) {
        float v = sb[d] + fv.x * sw[d] + fv.y * sw[HDIM + d]
                        + fv.z * sw[2 * HDIM + d] + fv.w * sw[3 * HDIM + d];
        hT[(size_t)d * N_NODES + n] = v;
    }
}

// ---------------- MLP via mma.sync, 4 sub-tiles per CTA --------------------------
__global__ void __launch_bounds__(256, 1) mlp_mma(
    const float* __restrict__ HT, const uint32_t* __restrict__ WM,
    const float* __restrict__ b1, const float* __restrict__ b2,
    float* __restrict__ Mout) {
    extern __shared__ __align__(16) uint32_t smu[];
    float* sbf = (float*)(smu + MSB_OFF);
    int tid = threadIdx.x;
    int base0 = blockIdx.x * (NSUB * MTILE);
    // stage weight images + biases once
    {
        const uint4* src = (const uint4*)WM;
        uint4* dst = (uint4*)smu;
        for (int i = tid; i < MSB_OFF / 4; i += 256) dst[i] = src[i];
    }
    if (tid < 50) sbf[tid] = b1[tid];
    else if (tid < 150) sbf[tid] = b2[tid - 50];

    int w = tid >> 5, lane = tid & 31;
    int q = lane & 3, l4 = lane >> 2;
    int r = w * 16 + l4;
    const uint32_t* A0 = smu + MA_OFF + r * 60;

    for (int s = 0; s < NSUB; s++) {
        int base = base0 + s * MTILE;
        if (base >= N_NODES) break;
        __syncthreads();   // weights ready / previous sub-tile's A reads + out copy done
        // stage A (h rows from transposed HT), split pairs, stride 60
        for (int idx = tid; idx < 56 * 128; idx += 256) {
            int kq = idx >> 7;
            int row = idx & 127;
            int k0 = 2 * kq, k1 = k0 + 1;
            float f0 = (k0 < 100) ? HT[(size_t)k0 * N_NODES + base + row] : 0.0f;
            float f1 = (k1 < 100) ? HT[(size_t)k1 * N_NODES + base + row] : 0.0f;
            uint32_t hi = (uint32_t)bfu(f0) | ((uint32_t)bfu(f1) << 16);
            float r0 = f0 - bff(f0), r1 = f1 - bff(f1);
            uint32_t lo = (uint32_t)bfu(r0) | ((uint32_t)bfu(r1) << 16);
            smu[MA_OFF + row * 60 + kq]      = hi;
            smu[MA_OFF + AW + row * 60 + kq] = lo;
        }
        __syncthreads();

        // ---- layer 1: 7 n-tiles over N=56 ----
        float c1[7][4];
        #pragma unroll
        for (int t = 0; t < 7; t++) { c1[t][0] = c1[t][1] = c1[t][2] = c1[t][3] = 0.f; }
        #pragma unroll
        for (int ks = 0; ks < 7; ks++) {
            uint32_t a00 = A0[ks * 8 + q],            a01 = A0[480 + ks * 8 + q];
            uint32_t a02 = A0[ks * 8 + 4 + q],        a03 = A0[480 + ks * 8 + 4 + q];
            uint32_t a10 = A0[AW + ks * 8 + q],       a11 = A0[AW + 480 + ks * 8 + q];
            uint32_t a12 = A0[AW + ks * 8 + 4 + q],   a13 = A0[AW + 480 + ks * 8 + 4 + q];
            const uint32_t* B0 = smu + (ks * 8 + q) * 56;
            const uint32_t* B1p = smu + (ks * 8 + 4 + q) * 56;
            #pragma unroll
            for (int t = 0; t < 7; t++) {
                int nb = t * 8 + l4;
                uint32_t b00 = B0[nb],        b01 = B1p[nb];
                uint32_t b10 = B0[BW1 + nb],  b11 = B1p[BW1 + nb];
                mma_bf16(c1[t], a00, a01, a02, a03, b00, b01);
                mma_bf16(c1[t], a10, a11, a12, a13, b00, b01);
                mma_bf16(c1[t], a00, a01, a02, a03, b10, b11);
            }
        }
        __syncthreads();   // layer-1 A reads done; A region reusable
        // bias + relu, store as layer-2 A image (fragment pair == A word, kq = t*4+q)
        #pragma unroll
        for (int t = 0; t < 7; t++) {
            int n0 = t * 8 + q * 2;
            int kq = t * 4 + q;
            float v0 = 0.f, v1 = 0.f, v2 = 0.f, v3 = 0.f;
            if (n0 < 50)     { float bb = sbf[n0];     v0 = fmaxf(c1[t][0] + bb, 0.f); v2 = fmaxf(c1[t][2] + bb, 0.f); }
            if (n0 + 1 < 50) { float bb = sbf[n0 + 1]; v1 = fmaxf(c1[t][1] + bb, 0.f); v3 = fmaxf(c1[t][3] + bb, 0.f); }
            uint32_t hi0 = (uint32_t)bfu(v0) | ((uint32_t)bfu(v1) << 16);
            uint32_t hi1 = (uint32_t)bfu(v2) | ((uint32_t)bfu(v3) << 16);
            uint32_t lo0 = (uint32_t)bfu(v0 - bff(v0)) | ((uint32_t)bfu(v1 - bff(v1)) << 16);
            uint32_t lo1 = (uint32_t)bfu(v2 - bff(v2)) | ((uint32_t)bfu(v3 - bff(v3)) << 16);
            smu[MA_OFF + r * 60 + kq]             = hi0;
            smu[MA_OFF + (r + 8) * 60 + kq]       = hi1;
            smu[MA_OFF + AW + r * 60 + kq]        = lo0;
            smu[MA_OFF + AW + (r + 8) * 60 + kq]  = lo1;
        }
        // zero K-padding words kq 28..31 (both splits)
        for (int idx = tid; idx < 128 * 4; idx += 256) {
            int row = idx >> 2, kqz = 28 + (idx & 3);
            smu[MA_OFF + row * 60 + kqz] = 0;
            smu[MA_OFF + AW + row * 60 + kqz] = 0;
        }
        __syncthreads();

        // ---- layer 2: 13 n-tiles over N=104, K=64 (4 ks) ----
        float c2[13][4];
        #pragma unroll
        for (int t = 0; t < 13; t++) { c2[t][0] = c2[t][1] = c2[t][2] = c2[t][3] = 0.f; }
        #pragma unroll
        for (int ks = 0; ks < 4; ks++) {
            uint32_t a00 = A0[ks * 8 + q],            a01 = A0[480 + ks * 8 + q];
            uint32_t a02 = A0[ks * 8 + 4 + q],        a03 = A0[480 + ks * 8 + 4 + q];
            uint32_t a10 = A0[AW + ks * 8 + q],       a11 = A0[AW + 480 + ks * 8 + q];
            uint32_t a12 = A0[AW + ks * 8 + 4 + q],   a13 = A0[AW + 480 + ks * 8 + 4 + q];
            const uint32_t* B0 = smu + MB2_OFF + (ks * 8 + q) * 104;
            const uint32_t* B1p = smu + MB2_OFF + (ks * 8 + 4 + q) * 104;
            #pragma unroll
            for (int t = 0; t < 13; t++) {
                int nb = t * 8 + l4;
                uint32_t b00 = B0[nb],        b01 = B1p[nb];
                uint32_t b10 = B0[BW2 + nb],  b11 = B1p[BW2 + nb];
                mma_bf16(c2[t], a00, a01, a02, a03, b00, b01);
                mma_bf16(c2[t], a10, a11, a12, a13, b00, b01);
                mma_bf16(c2[t], a00, a01, a02, a03, b10, b11);
            }
        }
        __syncthreads();   // layer-2 A reads done; A region reusable for out staging
        float* sst = (float*)(smu + MA_OFF);
        #pragma unroll
        for (int t = 0; t < 13; t++) {
            int n0 = t * 8 + q * 2;
            float b0v = (n0 < 100) ? sbf[50 + n0] : 0.f;
            float b1v = (n0 + 1 < 100) ? sbf[50 + n0 + 1] : 0.f;
            sst[n0 * 132 + r]             = c2[t][0] + b0v;
            sst[(n0 + 1) * 132 + r]       = c2[t][1] + b1v;
            sst[n0 * 132 + r + 8]         = c2[t][2] + b0v;
            sst[(n0 + 1) * 132 + r + 8]   = c2[t][3] + b1v;
        }
        __syncthreads();
        for (int idx = tid; idx < 25 * MTILE; idx += 256) {
            int row = idx & 127, c4 = (idx >> 7) * 4;
            float4 v = make_float4(sst[c4 * 132 + row], sst[(c4 + 1) * 132 + row],
                                   sst[(c4 + 2) * 132 + row], sst[(c4 + 3) * 132 + row]);
            *(float4*)(Mout + (size_t)(base + row) * HDIM + c4) = v;
        }
    }
}

// ---------------- warp-per-node CSR gather --------------------------------------
__global__ void __launch_bounds__(256) spmm_gather(
    const int* __restrict__ rptr, const int* __restrict__ csr,
    const float* __restrict__ m, float* __restrict__ msg) {
    int warp = (blockIdx.x * blockDim.x + threadIdx.x) >> 5;
    int lane = threadIdx.x & 31;
    if (warp >= N_NODES) return;
    int p0 = rptr[warp], p1 = rptr[warp + 1];
    float4 acc = make_float4(0.f, 0.f, 0.f, 0.f);
    for (int p = p0; p < p1; p++) {
        int s = csr[p];
        if (lane < 25) {
            float4 v = *(const float4*)(m + (size_t)s * HDIM + lane * 4);
            acc.x += v.x; acc.y += v.y; acc.z += v.z; acc.w += v.w;
        }
    }
    if (lane < 25)
        *(float4*)(msg + (size_t)warp * HDIM + lane * 4) = acc;
}

// ---------------- gi via mma.sync, 4 sub-tiles per CTA ---------------------------
template<int NT0, int NT>
__device__ __forceinline__ void gi_compute_half(
    const uint32_t* __restrict__ smu, float* __restrict__ outT,
    const float* __restrict__ Bih, int base, int w, int lane) {
    int q = lane & 3, l4 = lane >> 2;
    int r = w * 16 + l4;
    const uint32_t* A0 = smu + A_OFF + r * 60;
    float c[NT][4];
    #pragma unroll
    for (int t = 0; t < NT; t++) { c[t][0] = c[t][1] = c[t][2] = c[t][3] = 0.0f; }
    #pragma unroll
    for (int ks = 0; ks < 7; ks++) {
        uint32_t a00 = A0[ks * 8 + q],            a01 = A0[480 + ks * 8 + q];
        uint32_t a02 = A0[ks * 8 + 4 + q],        a03 = A0[480 + ks * 8 + 4 + q];
        uint32_t a10 = A0[AW + ks * 8 + q],       a11 = A0[AW + 480 + ks * 8 + q];
        uint32_t a12 = A0[AW + ks * 8 + 4 + q],   a13 = A0[AW + 480 + ks * 8 + 4 + q];
        const uint32_t* B0 = smu + (ks * 8 + q) * 312;
        const uint32_t* B1 = smu + (ks * 8 + 4 + q) * 312;
        #pragma unroll
        for (int t = 0; t < NT; t++) {
            int nb = (NT0 + t) * 8 + l4;
            uint32_t b00 = B0[nb],       b01 = B1[nb];
            uint32_t b10 = B0[BW + nb],  b11 = B1[BW + nb];
            mma_bf16(c[t], a00, a01, a02, a03, b00, b01);
            mma_bf16(c[t], a10, a11, a12, a13, b00, b01);
            mma_bf16(c[t], a00, a01, a02, a03, b10, b11);
        }
    }
    int node = base + r;
    #pragma unroll
    for (int t = 0; t < NT; t++) {
        int n0 = (NT0 + t) * 8 + q * 2;
        if (n0 < 300) {
            float bia = Bih[n0];
            outT[(size_t)n0 * N_NODES + node]     = c[t][0] + bia;
            outT[(size_t)n0 * N_NODES + node + 8] = c[t][2] + bia;
        }
        if (n0 + 1 < 300) {
            float bib = Bih[n0 + 1];
            outT[(size_t)(n0 + 1) * N_NODES + node]     = c[t][1] + bib;
            outT[(size_t)(n0 + 1) * N_NODES + node + 8] = c[t][3] + bib;
        }
    }
}

__global__ void __launch_bounds__(256, 1) gi_mma(
    const float* __restrict__ MSG, const uint32_t* __restrict__ GB,
    const float* __restrict__ Bih, float* __restrict__ outT) {
    extern __shared__ __align__(16) uint32_t smu[];
    int tid = threadIdx.x;
    int base0 = blockIdx.x * (NSUB * MTILE);
    // stage B once
    {
        const uint4* src = (const uint4*)GB;
        uint4* dst = (uint4*)smu;
        for (int i = tid; i < (2 * BW) / 4; i += 256) dst[i] = src[i];
    }
    int w = tid >> 5, lane = tid & 31;
    for (int s = 0; s < NSUB; s++) {
        int base = base0 + s * MTILE;
        if (base >= N_NODES) break;
        __syncthreads();   // B ready (s=0) / previous A reads done (s>0)
        for (int idx = tid; idx < 128 * 56; idx += 256) {
            int row = idx / 56;
            int kq = idx - row * 56;
            float2 v = make_float2(0.0f, 0.0f);
            if (kq < 50) v = *(const float2*)(MSG + (size_t)(base + row) * HDIM + 2 * kq);
            uint32_t hi = (uint32_t)bfu(v.x) | ((uint32_t)bfu(v.y) << 16);
            float rx = v.x - bff(v.x), ry = v.y - bff(v.y);
            uint32_t lo = (uint32_t)bfu(rx) | ((uint32_t)bfu(ry) << 16);
            smu[A_OFF + row * 60 + kq]      = hi;
            smu[A_OFF + AW + row * 60 + kq] = lo;
        }
        __syncthreads();
        gi_compute_half<0, 19>(smu, outT, Bih, base, w, lane);
        gi_compute_half<19, 20>(smu, outT, Bih, base, w, lane);
    }
}

// ---------------- tiled gate: h' = GRU(giT, hT) (scalar, proven) -----------------
__global__ void __launch_bounds__(GTB, 2) gate_tiled(
    const float* __restrict__ GIT,
    const float* __restrict__ HT,
    const float* __restrict__ W, const float* __restrict__ B,
    float* __restrict__ HoutT) {
    extern __shared__ float sm[];
    float* sxT = sm;
    float* sw  = sm + HDIM * SXS;
    float* sb  = sw + 6000;
    int base = blockIdx.x * MTILE;
    int lane = threadIdx.x & 31, wid = threadIdx.x >> 5;
    for (int i = threadIdx.x; i < HDIM3; i += GTB) sb[i] = B[i];
    for (int idx = threadIdx.x; idx < HDIM * 32; idx += GTB) {
        int k = idx >> 5, rq = idx & 31;
        *(float4*)(sxT + k * SXS + rq * 4) =
            *(const float4*)(HT + (size_t)k * N_NODES + base + rq * 4);
    }
    const float* xp = sxT + lane * 4;
    size_t rowoff = base + lane * 4;
    for (int ch = 0; ch < 5; ch++) {
        int d0 = ch * 20;
        __syncthreads();
        for (int i = threadIdx.x * 4; i < 6000; i += GTB * 4) {
            int k = i / 60, rem = i - k * 60;
            int g = rem / 20, j = rem - g * 20;
            *(float4*)(sw + i) = *(const float4*)(W + (size_t)k * HDIM3 + g * HDIM + d0 + j);
        }
        __syncthreads();
        int cl = wid * 2;
        u64 ar[4], az[4], an[4];
        {
            u64 br = *(const u64*)(sb + d0 + cl);
            u64 bz = *(const u64*)(sb + HDIM + d0 + cl);
            u64 bn = *(const u64*)(sb + 2 * HDIM + d0 + cl);
            #pragma unroll
            for (int r = 0; r < 4; r++) { ar[r] = br; az[r] = bz; an[r] = bn; }
        }
        for (int k = 0; k < HDIM; k++) {
            float4 a = *(const float4*)(xp + k * SXS);
            u64 a0 = pack2(a.x, a.x), a1p = pack2(a.y, a.y);
            u64 a2 = pack2(a.z, a.z), a3 = pack2(a.w, a.w);
            const float* wr = sw + k * 60 + cl;
            u64 wrv = *(const u64*)(wr);
            u64 wzv = *(const u64*)(wr + 20);
            u64 wnv = *(const u64*)(wr + 40);
            fma2(ar[0], a0, wrv); fma2(ar[1], a1p, wrv);
            fma2(ar[2], a2, wrv); fma2(ar[3], a3, wrv);
            fma2(az[0], a0, wzv); fma2(az[1], a1p, wzv);
            fma2(az[2], a2, wzv); fma2(az[3], a3, wzv);
            fma2(an[0], a0, wnv); fma2(an[1], a1p, wnv);
            fma2(an[2], a2, wnv); fma2(an[3], a3, wnv);
        }
        int c = d0 + cl;
        float4 gr0 = *(const float4*)(GIT + (size_t)c * N_NODES + rowoff);
        float4 gr1 = *(const float4*)(GIT + (size_t)(c + 1) * N_NODES + rowoff);
        float4 gz0 = *(const float4*)(GIT + (size_t)(HDIM + c) * N_NODES + rowoff);
        float4 gz1 = *(const float4*)(GIT + (size_t)(HDIM + c + 1) * N_NODES + rowoff);
        float4 gn0 = *(const float4*)(GIT + (size_t)(2 * HDIM + c) * N_NODES + rowoff);
        float4 gn1 = *(const float4*)(GIT + (size_t)(2 * HDIM + c + 1) * N_NODES + rowoff);
        float4 h0 = *(const float4*)(sxT + c * SXS + lane * 4);
        float4 h1 = *(const float4*)(sxT + (c + 1) * SXS + lane * 4);
        float4 o0, o1;
        {
            const float* grp0 = &gr0.x; const float* grp1 = &gr1.x;
            const float* gzp0 = &gz0.x; const float* gzp1 = &gz1.x;
            const float* gnp0 = &gn0.x; const float* gnp1 = &gn1.x;
            const float* hp0 = &h0.x;  const float* hp1 = &h1.x;
            float* op0 = &o0.x; float* op1 = &o1.x;
            #pragma unroll
            for (int r = 0; r < 4; r++) {
                float2 hr = unpack2(ar[r]);
                float2 hz = unpack2(az[r]);
                float2 hn = unpack2(an[r]);
                float r0 = fsigmoid(grp0[r] + hr.x);
                float r1 = fsigmoid(grp1[r] + hr.y);
                float z0 = fsigmoid(gzp0[r] + hz.x);
                float z1 = fsigmoid(gzp1[r] + hz.y);
                float n0 = ftanh_(gnp0[r] + r0 * hn.x);
                float n1 = ftanh_(gnp1[r] + r1 * hn.y);
                op0[r] = (1.0f - z0) * n0 + z0 * hp0[r];
                op1[r] = (1.0f - z1) * n1 + z1 * hp1[r];
            }
        }
        *(float4*)(HoutT + (size_t)c * N_NODES + rowoff) = o0;
        *(float4*)(HoutT + (size_t)(c + 1) * N_NODES + rowoff) = o1;
    }
}

// ---------------- classifier from transposed h ----------------------------------
__global__ void __launch_bounds__(256) classify_kernel(
    const float* __restrict__ HT,
    const float* __restrict__ w1, const float* __restrict__ b1,
    const float* __restrict__ w2, const float* __restrict__ b2,
    float* __restrict__ out) {
    __shared__ float s1[HDIM * CDIM];
    __shared__ float sb1[CDIM];
    __shared__ float s2[CDIM];
    __shared__ float sb2;
    for (int i = threadIdx.x; i < HDIM * CDIM; i += blockDim.x) s1[i] = w1[i];
    for (int i = threadIdx.x; i < CDIM; i += blockDim.x) { sb1[i] = b1[i]; s2[i] = w2[i]; }
    if (threadIdx.x == 0) sb2 = b2[0];
    __syncthreads();
    int n = blockIdx.x * blockDim.x + threadIdx.x;
    if (n >= N_NODES) return;
    float a[CDIM];
    #pragma unroll
    for (int j = 0; j < CDIM; j++) a[j] = sb1[j];
    for (int k = 0; k < HDIM; k++) {
        float xv = HT[(size_t)k * N_NODES + n];
        const float* wr = s1 + k * CDIM;
        #pragma unroll
        for (int j = 0; j < CDIM; j++) a[j] = fmaf(xv, wr[j], a[j]);
    }
    float r = sb2;
    #pragma unroll
    for (int j = 0; j < CDIM; j++) r = fmaf(fmaxf(a[j], 0.0f), s2[j], r);
    out[n] = r;
}

// ---------------- host orchestration --------------------------------------------
extern "C" void kernel_launch(void* const* d_in, const int* in_sizes, int n_in,
                              void* d_out, int out_size) {
    const float* features = (const float*)d_in[0];
    const void*  e_row    = d_in[1];
    const void*  e_col    = d_in[2];
    const float* init_w   = (const float*)d_in[3];
    const float* init_b   = (const float*)d_in[4];
    const float* fm_w1 = (const float*)d_in[5],  *fm_b1 = (const float*)d_in[6];
    const float* fm_w2 = (const float*)d_in[7],  *fm_b2 = (const float*)d_in[8];
    const float* bm_w1 = (const float*)d_in[9],  *bm_b1 = (const float*)d_in[10];
    const float* bm_w2 = (const float*)d_in[11], *bm_b2 = (const float*)d_in[12];
    const float* fg_wih = (const float*)d_in[13], *fg_whh = (const float*)d_in[14];
    const float* fg_bih = (const float*)d_in[15], *fg_bhh = (const float*)d_in[16];
    const float* bg_wih = (const float*)d_in[17], *bg_whh = (const float*)d_in[18];
    const float* bg_bih = (const float*)d_in[19], *bg_bhh = (const float*)d_in[20];
    const float* cl_w1 = (const float*)d_in[21], *cl_b1 = (const float*)d_in[22];
    const float* cl_w2 = (const float*)d_in[23], *cl_b2 = (const float*)d_in[24];
    float* out = (float*)d_out;

    float *h, *h2, *m, *msg, *gi;
    int *row_i, *col_i, *degF, *degB, *rptrF, *rptrB, *curF, *curB, *csrF, *csrB, *incl, *bsums;
    uint32_t *wbia, *wmlp;
    cudaGetSymbolAddress((void**)&h,     g_h);
    cudaGetSymbolAddress((void**)&h2,    g_h2);
    cudaGetSymbolAddress((void**)&m,     g_m);
    cudaGetSymbolAddress((void**)&msg,   g_msg);
    cudaGetSymbolAddress((void**)&gi,    g_gi);
    cudaGetSymbolAddress((void**)&wbia,  g_wbia);
    cudaGetSymbolAddress((void**)&wmlp,  g_wmlp);
    cudaGetSymbolAddress((void**)&row_i, g_row);
    cudaGetSymbolAddress((void**)&col_i, g_col);
    cudaGetSymbolAddress((void**)&degF,  g_degF);
    cudaGetSymbolAddress((void**)&degB,  g_degB);
    cudaGetSymbolAddress((void**)&rptrF, g_rptrF);
    cudaGetSymbolAddress((void**)&rptrB, g_rptrB);
    cudaGetSymbolAddress((void**)&curF,  g_curF);
    cudaGetSymbolAddress((void**)&curB,  g_curB);
    cudaGetSymbolAddress((void**)&csrF,  g_csrF);
    cudaGetSymbolAddress((void**)&csrB,  g_csrB);
    cudaGetSymbolAddress((void**)&incl,  g_incl);
    cudaGetSymbolAddress((void**)&bsums, g_bsums);

    uint32_t* wbia_f = wbia;
    uint32_t* wbia_b = wbia + 2 * BW;
    uint32_t* wmlp_f = wmlp;
    uint32_t* wmlp_b = wmlp + MSB_OFF;

    const size_t smem_gate = (size_t)(HDIM * SXS + 6000 + 300) * sizeof(float);
    cudaFuncSetAttribute(gate_tiled, cudaFuncAttributeMaxDynamicSharedMemorySize, (int)smem_gate);
    cudaFuncSetAttribute(gi_mma,     cudaFuncAttributeMaxDynamicSharedMemorySize, GI_SMEM);
    cudaFuncSetAttribute(mlp_mma,    cudaFuncAttributeMaxDynamicSharedMemorySize, MLP_SMEM);

    const int GT    = N_NODES / MTILE;                     // 3125
    const int GT4   = (N_NODES + NSUB * MTILE - 1) / (NSUB * MTILE);   // 782
    const int GN256 = (N_NODES + 255) / 256;
    const int GE    = (N_EDGES + 255) / 256;
    const int GW    = (int)(((long long)N_NODES * 32 + 255) / 256);
    const int NB    = (N_NODES + 1023) / 1024;
    const int GP    = (BW + 255) / 256;
    const int GPM   = (BW1 + BW2 + 255) / 256;

    // ---- preprocessing ----
    detect_kernel<<<1, 32>>>((const unsigned int*)e_row);
    convert_kernel<<<GE, 256>>>(e_row, e_col, row_i, col_i);
    cudaMemsetAsync(degF, 0, N_NODES * sizeof(int));
    cudaMemsetAsync(degB, 0, N_NODES * sizeof(int));
    deg_kernel<<<GE, 256>>>(row_i, col_i, degF, degB);
    scan_block<<<NB, 1024>>>(degF, incl, bsums, N_NODES);
    scan_sums<<<1, 32>>>(bsums, NB);
    scan_final<<<(N_NODES + 256) / 256, 256>>>(incl, degF, bsums, rptrF, N_NODES);
    scan_block<<<NB, 1024>>>(degB, incl, bsums, N_NODES);
    scan_sums<<<1, 32>>>(bsums, NB);
    scan_final<<<(N_NODES + 256) / 256, 256>>>(incl, degB, bsums, rptrB, N_NODES);
    cudaMemcpyAsync(curF, rptrF, N_NODES * sizeof(int), cudaMemcpyDeviceToDevice);
    cudaMemcpyAsync(curB, rptrB, N_NODES * sizeof(int), cudaMemcpyDeviceToDevice);
    scatter_kernel<<<GE, 256>>>(row_i, col_i, curF, curB, csrF, csrB);

    prep_wb<<<GP, 256>>>(fg_wih, wbia_f);
    prep_wb<<<GP, 256>>>(bg_wih, wbia_b);
    prep_wmlp<<<GPM, 256>>>(fm_w1, fm_w2, wmlp_f);
    prep_wmlp<<<GPM, 256>>>(bm_w1, bm_w2, wmlp_b);

    initT_kernel<<<GT, MTILE>>>(features, init_w, init_b, h);

    float* hc = h;
    float* hn = h2;

    for (int rnd = 0; rnd < 20; rnd++) {
        // forward pass
        mlp_mma<<<GT4, 256, MLP_SMEM>>>(hc, wmlp_f, fm_b1, fm_b2, m);
        spmm_gather<<<GW, 256>>>(rptrF, csrF, m, msg);
        gi_mma<<<GT4, 256, GI_SMEM>>>(msg, wbia_f, fg_bih, gi);
        gate_tiled<<<GT, GTB, smem_gate>>>(gi, hc, fg_whh, fg_bhh, hn);
        { float* t = hc; hc = hn; hn = t; }
        // backward pass
        mlp_mma<<<GT4, 256, MLP_SMEM>>>(hc, wmlp_b, bm_b1, bm_b2, m);
        spmm_gather<<<GW, 256>>>(rptrB, csrB, m, msg);
        gi_mma<<<GT4, 256, GI_SMEM>>>(msg, wbia_b, bg_bih, gi);
        gate_tiled<<<GT, GTB, smem_gate>>>(gi, hc, bg_whh, bg_bhh, hn);
        { float* t = hc; hc = hn; hn = t; }
    }

    classify_kernel<<<GN256, 256>>>(hc, cl_w1, cl_b1, cl_w2, cl_b2, out);
}

// round 11
// speedup vs baseline: 1.0867x; 1.0867x over previous
#include <cuda_runtime.h>
#include <cuda_bf16.h>
#include <cstdint>

#define N_NODES 400000
#define N_EDGES 1600000
#define HDIM 100
#define HDIM3 300
#define ADIM 50
#define CDIM 30
#define GTB 320          // threads for scalar tiled GEMM kernels
#define MTILE 128        // rows per CTA (400000 = 128 * 3125 exactly)
#define SXS 132          // k-major tile row stride

// ---- mma.sync gi GEMM geometry ----
#define BW 17472                 // 56*312 words per B split
#define AW 7680                  // 128*60 words per A split
#define A_OFF (2*BW)             // A base word offset in smem
#define GI_SMEM ((2*BW + 2*AW) * 4)   // 201216 bytes

typedef unsigned long long u64;

// ---------------- scratch (device globals) -------------------------------------
__device__ __align__(16) float g_h  [N_NODES * HDIM];
__device__ __align__(16) float g_h2 [N_NODES * HDIM];
__device__ __align__(16) float g_m  [N_NODES * HDIM];
__device__ __align__(16) float g_msg[N_NODES * HDIM];
__device__ __align__(16) float g_gi [(size_t)N_NODES * HDIM3];
__device__ __align__(16) uint32_t g_wbia[2][2 * BW];   // fwd/bwd wih bf16-split images
__device__ int g_row[N_EDGES];
__device__ int g_col[N_EDGES];
__device__ int g_is64;
__device__ int g_degF[N_NODES];
__device__ int g_degB[N_NODES];
__device__ int g_rptrF[N_NODES + 1];
__device__ int g_rptrB[N_NODES + 1];
__device__ int g_curF[N_NODES];
__device__ int g_curB[N_NODES];
__device__ int g_csrF[N_EDGES];
__device__ int g_csrB[N_EDGES];
__device__ int g_incl[N_NODES];
__device__ int g_bsums[512];

// ---------------- helpers --------------------------------------------------------
__device__ __forceinline__ u64 pack2(float x, float y) {
    u64 r; asm("mov.b64 %0, {%1, %2};" : "=l"(r) : "f"(x), "f"(y)); return r;
}
__device__ __forceinline__ float2 unpack2(u64 v) {
    float2 r; asm("mov.b64 {%0, %1}, %2;" : "=f"(r.x), "=f"(r.y) : "l"(v)); return r;
}
__device__ __forceinline__ void fma2(u64& d, u64 a, u64 b) {
    asm("fma.rn.f32x2 %0, %1, %2, %0;" : "+l"(d) : "l"(a), "l"(b));
}
__device__ __forceinline__ float ex2a(float x) {
    float r; asm("ex2.approx.f32 %0, %1;" : "=f"(r) : "f"(x)); return r;
}
__device__ __forceinline__ float rcpa(float x) {
    float r; asm("rcp.approx.f32 %0, %1;" : "=f"(r) : "f"(x)); return r;
}
// sigmoid(x) = 1/(1+e^-x) = rcp(1 + 2^(-x*log2e))   (saturates correctly at +-inf)
__device__ __forceinline__ float fsigmoid(float x) {
    return rcpa(1.0f + ex2a(-1.4426950408889634f * x));
}
// tanh(x) = 1 - 2/(e^2x + 1) = 1 - 2*rcp(2^(2x*log2e) + 1)
__device__ __forceinline__ float ftanh_(float x) {
    float e = ex2a(2.8853900817779268f * x);
    return fmaf(-2.0f, rcpa(e + 1.0f), 1.0f);
}
__device__ __forceinline__ unsigned short bfu(float x) {
    __nv_bfloat16 b = __float2bfloat16(x);
    return *reinterpret_cast<unsigned short*>(&b);
}
__device__ __forceinline__ float bff(float x) {
    return __bfloat162float(__float2bfloat16(x));
}
__device__ __forceinline__ void mma_bf16(float c[4],
    uint32_t a0, uint32_t a1, uint32_t a2, uint32_t a3,
    uint32_t b0, uint32_t b1) {
    asm volatile(
        "mma.sync.aligned.m16n8k16.row.col.f32.bf16.bf16.f32 "
        "{%0,%1,%2,%3}, {%4,%5,%6,%7}, {%8,%9}, {%0,%1,%2,%3};"
        : "+f"(c[0]), "+f"(c[1]), "+f"(c[2]), "+f"(c[3])
        : "r"(a0), "r"(a1), "r"(a2), "r"(a3), "r"(b0), "r"(b1));
}

// ---------------- edge dtype detection & normalization -------------------------
__global__ void detect_kernel(const unsigned int* __restrict__ w) {
    unsigned int v = w[2 * threadIdx.x + 1];
    unsigned int any = __ballot_sync(0xffffffffu, v != 0u);
    if (threadIdx.x == 0) g_is64 = (any == 0u) ? 1 : 0;
}

__global__ void convert_kernel(const void* __restrict__ rp, const void* __restrict__ cp,
                               int* __restrict__ ro, int* __restrict__ co) {
    int e = blockIdx.x * blockDim.x + threadIdx.x;
    if (e >= N_EDGES) return;
    if (g_is64) {
        ro[e] = (int)((const long long*)rp)[e];
        co[e] = (int)((const long long*)cp)[e];
    } else {
        ro[e] = ((const int*)rp)[e];
        co[e] = ((const int*)cp)[e];
    }
}

// ---------------- CSR build ------------------------------------------------------
__global__ void deg_kernel(const int* __restrict__ row, const int* __restrict__ col,
                           int* __restrict__ degF, int* __restrict__ degB) {
    int e = blockIdx.x * blockDim.x + threadIdx.x;
    if (e >= N_EDGES) return;
    atomicAdd(&degF[row[e]], 1);
    atomicAdd(&degB[col[e]], 1);
}

__global__ void scan_block(const int* __restrict__ deg, int* __restrict__ incl,
                           int* __restrict__ bsums, int n) {
    __shared__ int s[1024];
    int i = blockIdx.x * 1024 + threadIdx.x;
    int v = (i < n) ? deg[i] : 0;
    s[threadIdx.x] = v;
    __syncthreads();
    #pragma unroll
    for (int off = 1; off < 1024; off <<= 1) {
        int t = (threadIdx.x >= off) ? s[threadIdx.x - off] : 0;
        __syncthreads();
        s[threadIdx.x] += t;
        __syncthreads();
    }
    if (i < n) incl[i] = s[threadIdx.x];
    if (threadIdx.x == 1023) bsums[blockIdx.x] = s[1023];
}

__global__ void scan_sums(int* __restrict__ bsums, int nb) {
    if (threadIdx.x == 0) {
        int acc = 0;
        for (int b = 0; b < nb; b++) { int t = bsums[b]; bsums[b] = acc; acc += t; }
    }
}

__global__ void scan_final(const int* __restrict__ incl, const int* __restrict__ deg,
                           const int* __restrict__ bsums, int* __restrict__ rptr, int n) {
    int i = blockIdx.x * 256 + threadIdx.x;
    if (i < n) rptr[i] = incl[i] - deg[i] + bsums[i >> 10];
    if (i == n) rptr[n] = N_EDGES;
}

__global__ void scatter_kernel(const int* __restrict__ row, const int* __restrict__ col,
                               int* __restrict__ curF, int* __restrict__ curB,
                               int* __restrict__ csrF, int* __restrict__ csrB) {
    int e = blockIdx.x * blockDim.x + threadIdx.x;
    if (e >= N_EDGES) return;
    int r = row[e], c = col[e];
    int pF = atomicAdd(&curF[r], 1);
    csrF[pF] = c;
    int pB = atomicAdd(&curB[c], 1);
    csrB[pB] = r;
}

// ---------------- weight prep: Wih[100][300] -> 2 bf16-split pair images --------
__global__ void prep_wb(const float* __restrict__ W, uint32_t* __restrict__ o) {
    int e = blockIdx.x * 256 + threadIdx.x;
    if (e >= BW) return;
    int kq = e / 312, n = e - kq * 312;
    int k0 = 2 * kq, k1 = k0 + 1;
    float w0 = (k0 < 100 && n < 300) ? W[k0 * 300 + n] : 0.0f;
    float w1 = (k1 < 100 && n < 300) ? W[k1 * 300 + n] : 0.0f;
    o[e] = (uint32_t)bfu(w0) | ((uint32_t)bfu(w1) << 16);
    float r0 = w0 - bff(w0), r1 = w1 - bff(w1);
    o[BW + e] = (uint32_t)bfu(r0) | ((uint32_t)bfu(r1) << 16);
}

// ---------------- h0_T[d][n] = (features @ init_w + init_b)^T ------------------
__global__ void initT_kernel(const float* __restrict__ f, const float* __restrict__ w,
                             const float* __restrict__ b, float* __restrict__ hT) {
    __shared__ float sw[4 * HDIM];
    __shared__ float sb[HDIM];
    for (int i = threadIdx.x; i < 4 * HDIM; i += blockDim.x) sw[i] = w[i];
    for (int i = threadIdx.x; i < HDIM; i += blockDim.x) sb[i] = b[i];
    __syncthreads();
    int n = blockIdx.x * blockDim.x + threadIdx.x;
    float4 fv = *(const float4*)(f + (size_t)n * 4);
    #pragma unroll 4
    for (int d = 0; d < HDIM; d++) {
        float v = sb[d] + fv.x * sw[d] + fv.y * sw[HDIM + d]
                        + fv.z * sw[2 * HDIM + d] + fv.w * sw[3 * HDIM + d];
        hT[(size_t)d * N_NODES + n] = v;
    }
}

// ---------------- scalar tiled MLP (layer1 now packed f32x2) --------------------
__global__ void __launch_bounds__(GTB, 2) mlp_tiled(
    const float* __restrict__ HT,
    const float* __restrict__ w1, const float* __restrict__ b1,
    const float* __restrict__ w2, const float* __restrict__ b2,
    float* __restrict__ Mout) {
    extern __shared__ float sm[];
    float* sxT = sm;
    float* sw1 = sm + HDIM * SXS;
    float* sw2 = sw1 + 5000;
    float* sb  = sw2 + 5000;
    int base = blockIdx.x * MTILE;
    int lane = threadIdx.x & 31, wid = threadIdx.x >> 5;

    for (int i = threadIdx.x; i < 5000; i += GTB) { sw1[i] = w1[i]; sw2[i] = w2[i]; }
    if (threadIdx.x < 50) sb[threadIdx.x] = b1[threadIdx.x];
    else if (threadIdx.x < 150) sb[threadIdx.x] = b2[threadIdx.x - 50];
    for (int idx = threadIdx.x; idx < HDIM * 32; idx += GTB) {
        int k = idx >> 5, rq = idx & 31;
        *(float4*)(sxT + k * SXS + rq * 4) =
            *(const float4*)(HT + (size_t)k * N_NODES + base + rq * 4);
    }
    __syncthreads();

    // layer 1: row-pairs packed in f32x2
    u64 a01[5], a23[5];
    #pragma unroll
    for (int j = 0; j < 5; j++) {
        float b = sb[wid * 5 + j];
        u64 bb = pack2(b, b);
        a01[j] = bb; a23[j] = bb;
    }
    const float* xp = sxT + lane * 4;
    for (int k = 0; k < HDIM; k++) {
        float4 a = *(const float4*)(xp + k * SXS);
        u64 axy = pack2(a.x, a.y), azw = pack2(a.z, a.w);
        const float* wr = sw1 + k * ADIM + wid * 5;
        #pragma unroll
        for (int j = 0; j < 5; j++) {
            float wv = wr[j];
            u64 w2 = pack2(wv, wv);
            fma2(a01[j], axy, w2);
            fma2(a23[j], azw, w2);
        }
    }
    __syncthreads();
    #pragma unroll
    for (int j = 0; j < 5; j++) {
        float2 v01 = unpack2(a01[j]);
        float2 v23 = unpack2(a23[j]);
        float* dst = sxT + (wid * 5 + j) * SXS + lane * 4;
        dst[0] = fmaxf(v01.x, 0.0f);
        dst[1] = fmaxf(v01.y, 0.0f);
        dst[2] = fmaxf(v23.x, 0.0f);
        dst[3] = fmaxf(v23.y, 0.0f);
    }
    __syncthreads();

    u64 acc[20];
    const u64* bb = (const u64*)(sb + 50 + wid * 10);
    #pragma unroll
    for (int r = 0; r < 4; r++)
        #pragma unroll
        for (int j = 0; j < 5; j++) acc[r * 5 + j] = bb[j];
    for (int k = 0; k < ADIM; k++) {
        float4 a = *(const float4*)(xp + k * SXS);
        u64 a0 = pack2(a.x, a.x), a1p = pack2(a.y, a.y);
        u64 a2 = pack2(a.z, a.z), a3 = pack2(a.w, a.w);
        const float* wr = sw2 + k * HDIM + wid * 10;
        #pragma unroll
        for (int j = 0; j < 5; j++) {
            u64 wv = *(const u64*)(wr + 2 * j);
            fma2(acc[j],      a0,  wv);
            fma2(acc[5 + j],  a1p, wv);
            fma2(acc[10 + j], a2,  wv);
            fma2(acc[15 + j], a3,  wv);
        }
    }
    __syncthreads();
    #pragma unroll
    for (int j = 0; j < 5; j++) {
        int c = wid * 10 + 2 * j;
        #pragma unroll
        for (int r = 0; r < 4; r++) {
            float2 v = unpack2(acc[r * 5 + j]);
            sxT[c * SXS + lane * 4 + r]       = v.x;
            sxT[(c + 1) * SXS + lane * 4 + r] = v.y;
        }
    }
    __syncthreads();
    for (int idx = threadIdx.x; idx < 25 * MTILE; idx += GTB) {
        int row = idx & 127, c4 = (idx >> 7) * 4;
        float4 v = make_float4(sxT[c4 * SXS + row], sxT[(c4 + 1) * SXS + row],
                               sxT[(c4 + 2) * SXS + row], sxT[(c4 + 3) * SXS + row]);
        *(float4*)(Mout + (size_t)(base + row) * HDIM + c4) = v;
    }
}

// ---------------- warp-per-node CSR gather --------------------------------------
__global__ void __launch_bounds__(256) spmm_gather(
    const int* __restrict__ rptr, const int* __restrict__ csr,
    const float* __restrict__ m, float* __restrict__ msg) {
    int warp = (blockIdx.x * blockDim.x + threadIdx.x) >> 5;
    int lane = threadIdx.x & 31;
    if (warp >= N_NODES) return;
    int p0 = rptr[warp], p1 = rptr[warp + 1];
    float4 acc = make_float4(0.f, 0.f, 0.f, 0.f);
    for (int p = p0; p < p1; p++) {
        int s = csr[p];   // same address across warp -> broadcast
        if (lane < 25) {
            float4 v = *(const float4*)(m + (size_t)s * HDIM + lane * 4);
            acc.x += v.x; acc.y += v.y; acc.z += v.z; acc.w += v.w;
        }
    }
    if (lane < 25)
        *(float4*)(msg + (size_t)warp * HDIM + lane * 4) = acc;
}

// ---------------- gi via mma.sync: giT = (msg @ Wih + bih)^T --------------------
template<int NT0, int NT>
__device__ __forceinline__ void gi_compute_half(
    const uint32_t* __restrict__ smu, float* __restrict__ outT,
    const float* __restrict__ Bih, int base, int w, int lane) {
    int q = lane & 3, l4 = lane >> 2;
    int r = w * 16 + l4;
    const uint32_t* A0 = smu + A_OFF + r * 60;
    float c[NT][4];
    #pragma unroll
    for (int t = 0; t < NT; t++) { c[t][0] = c[t][1] = c[t][2] = c[t][3] = 0.0f; }
    #pragma unroll
    for (int ks = 0; ks < 7; ks++) {
        uint32_t a00 = A0[ks * 8 + q],            a01 = A0[480 + ks * 8 + q];
        uint32_t a02 = A0[ks * 8 + 4 + q],        a03 = A0[480 + ks * 8 + 4 + q];
        uint32_t a10 = A0[AW + ks * 8 + q],       a11 = A0[AW + 480 + ks * 8 + q];
        uint32_t a12 = A0[AW + ks * 8 + 4 + q],   a13 = A0[AW + 480 + ks * 8 + 4 + q];
        const uint32_t* B0 = smu + (ks * 8 + q) * 312;
        const uint32_t* B1 = smu + (ks * 8 + 4 + q) * 312;
        #pragma unroll
        for (int t = 0; t < NT; t++) {
            int nb = (NT0 + t) * 8 + l4;
            uint32_t b00 = B0[nb],       b01 = B1[nb];
            uint32_t b10 = B0[BW + nb],  b11 = B1[BW + nb];
            mma_bf16(c[t], a00, a01, a02, a03, b00, b01);   // aHi * bHi
            mma_bf16(c[t], a10, a11, a12, a13, b00, b01);   // aLo * bHi
            mma_bf16(c[t], a00, a01, a02, a03, b10, b11);   // aHi * bLo
        }
    }
    int node = base + r;
    #pragma unroll
    for (int t = 0; t < NT; t++) {
        int n0 = (NT0 + t) * 8 + q * 2;
        if (n0 < 300) {
            float bia = Bih[n0];
            outT[(size_t)n0 * N_NODES + node]     = c[t][0] + bia;
            outT[(size_t)n0 * N_NODES + node + 8] = c[t][2] + bia;
        }
        if (n0 + 1 < 300) {
            float bib = Bih[n0 + 1];
            outT[(size_t)(n0 + 1) * N_NODES + node]     = c[t][1] + bib;
            outT[(size_t)(n0 + 1) * N_NODES + node + 8] = c[t][3] + bib;
        }
    }
}

__global__ void __launch_bounds__(256, 1) gi_mma(
    const float* __restrict__ MSG, const uint32_t* __restrict__ GB,
    const float* __restrict__ Bih, float* __restrict__ outT) {
    extern __shared__ __align__(16) uint32_t smu[];
    int tid = threadIdx.x;
    int base = blockIdx.x * MTILE;
    // stage B splits (verbatim pair image)
    {
        const uint4* src = (const uint4*)GB;
        uint4* dst = (uint4*)smu;
        for (int i = tid; i < (2 * BW) / 4; i += 256) dst[i] = src[i];
    }
    // stage A: msg rows -> bf16 split pairs, padded stride 60
    for (int idx = tid; idx < 128 * 56; idx += 256) {
        int row = idx / 56;
        int kq = idx - row * 56;
        float2 v = make_float2(0.0f, 0.0f);
        if (kq < 50) v = *(const float2*)(MSG + (size_t)(base + row) * HDIM + 2 * kq);
        uint32_t hi = (uint32_t)bfu(v.x) | ((uint32_t)bfu(v.y) << 16);
        float rx = v.x - bff(v.x), ry = v.y - bff(v.y);
        uint32_t lo = (uint32_t)bfu(rx) | ((uint32_t)bfu(ry) << 16);
        smu[A_OFF + row * 60 + kq]      = hi;
        smu[A_OFF + AW + row * 60 + kq] = lo;
    }
    __syncthreads();
    int w = tid >> 5, lane = tid & 31;
    gi_compute_half<0, 19>(smu, outT, Bih, base, w, lane);
    gi_compute_half<19, 20>(smu, outT, Bih, base, w, lane);
}

// ---------------- tiled gate: h' = GRU(giT, hT) (scalar, fast activations) ------
__global__ void __launch_bounds__(GTB, 2) gate_tiled(
    const float* __restrict__ GIT,
    const float* __restrict__ HT,
    const float* __restrict__ W, const float* __restrict__ B,
    float* __restrict__ HoutT) {
    extern __shared__ float sm[];
    float* sxT = sm;
    float* sw  = sm + HDIM * SXS;
    float* sb  = sw + 6000;
    int base = blockIdx.x * MTILE;
    int lane = threadIdx.x & 31, wid = threadIdx.x >> 5;
    for (int i = threadIdx.x; i < HDIM3; i += GTB) sb[i] = B[i];
    for (int idx = threadIdx.x; idx < HDIM * 32; idx += GTB) {
        int k = idx >> 5, rq = idx & 31;
        *(float4*)(sxT + k * SXS + rq * 4) =
            *(const float4*)(HT + (size_t)k * N_NODES + base + rq * 4);
    }
    const float* xp = sxT + lane * 4;
    size_t rowoff = base + lane * 4;
    for (int ch = 0; ch < 5; ch++) {
        int d0 = ch * 20;
        __syncthreads();
        for (int i = threadIdx.x * 4; i < 6000; i += GTB * 4) {
            int k = i / 60, rem = i - k * 60;
            int g = rem / 20, j = rem - g * 20;
            *(float4*)(sw + i) = *(const float4*)(W + (size_t)k * HDIM3 + g * HDIM + d0 + j);
        }
        __syncthreads();
        int cl = wid * 2;
        u64 ar[4], az[4], an[4];
        {
            u64 br = *(const u64*)(sb + d0 + cl);
            u64 bz = *(const u64*)(sb + HDIM + d0 + cl);
            u64 bn = *(const u64*)(sb + 2 * HDIM + d0 + cl);
            #pragma unroll
            for (int r = 0; r < 4; r++) { ar[r] = br; az[r] = bz; an[r] = bn; }
        }
        for (int k = 0; k < HDIM; k++) {
            float4 a = *(const float4*)(xp + k * SXS);
            u64 a0 = pack2(a.x, a.x), a1p = pack2(a.y, a.y);
            u64 a2 = pack2(a.z, a.z), a3 = pack2(a.w, a.w);
            const float* wr = sw + k * 60 + cl;
            u64 wrv = *(const u64*)(wr);
            u64 wzv = *(const u64*)(wr + 20);
            u64 wnv = *(const u64*)(wr + 40);
            fma2(ar[0], a0, wrv); fma2(ar[1], a1p, wrv);
            fma2(ar[2], a2, wrv); fma2(ar[3], a3, wrv);
            fma2(az[0], a0, wzv); fma2(az[1], a1p, wzv);
            fma2(az[2], a2, wzv); fma2(az[3], a3, wzv);
            fma2(an[0], a0, wnv); fma2(an[1], a1p, wnv);
            fma2(an[2], a2, wnv); fma2(an[3], a3, wnv);
        }
        int c = d0 + cl;
        float4 gr0 = *(const float4*)(GIT + (size_t)c * N_NODES + rowoff);
        float4 gr1 = *(const float4*)(GIT + (size_t)(c + 1) * N_NODES + rowoff);
        float4 gz0 = *(const float4*)(GIT + (size_t)(HDIM + c) * N_NODES + rowoff);
        float4 gz1 = *(const float4*)(GIT + (size_t)(HDIM + c + 1) * N_NODES + rowoff);
        float4 gn0 = *(const float4*)(GIT + (size_t)(2 * HDIM + c) * N_NODES + rowoff);
        float4 gn1 = *(const float4*)(GIT + (size_t)(2 * HDIM + c + 1) * N_NODES + rowoff);
        float4 h0 = *(const float4*)(sxT + c * SXS + lane * 4);
        float4 h1 = *(const float4*)(sxT + (c + 1) * SXS + lane * 4);
        float4 o0, o1;
        {
            const float* grp0 = &gr0.x; const float* grp1 = &gr1.x;
            const float* gzp0 = &gz0.x; const float* gzp1 = &gz1.x;
            const float* gnp0 = &gn0.x; const float* gnp1 = &gn1.x;
            const float* hp0 = &h0.x;  const float* hp1 = &h1.x;
            float* op0 = &o0.x; float* op1 = &o1.x;
            #pragma unroll
            for (int r = 0; r < 4; r++) {
                float2 hr = unpack2(ar[r]);
                float2 hz = unpack2(az[r]);
                float2 hn = unpack2(an[r]);
                float r0 = fsigmoid(grp0[r] + hr.x);
                float r1 = fsigmoid(grp1[r] + hr.y);
                float z0 = fsigmoid(gzp0[r] + hz.x);
                float z1 = fsigmoid(gzp1[r] + hz.y);
                float n0 = ftanh_(gnp0[r] + r0 * hn.x);
                float n1 = ftanh_(gnp1[r] + r1 * hn.y);
                op0[r] = (1.0f - z0) * n0 + z0 * hp0[r];
                op1[r] = (1.0f - z1) * n1 + z1 * hp1[r];
            }
        }
        *(float4*)(HoutT + (size_t)c * N_NODES + rowoff) = o0;
        *(float4*)(HoutT + (size_t)(c + 1) * N_NODES + rowoff) = o1;
    }
}

// ---------------- classifier from transposed h ----------------------------------
__global__ void __launch_bounds__(256) classify_kernel(
    const float* __restrict__ HT,
    const float* __restrict__ w1, const float* __restrict__ b1,
    const float* __restrict__ w2, const float* __restrict__ b2,
    float* __restrict__ out) {
    __shared__ float s1[HDIM * CDIM];
    __shared__ float sb1[CDIM];
    __shared__ float s2[CDIM];
    __shared__ float sb2;
    for (int i = threadIdx.x; i < HDIM * CDIM; i += blockDim.x) s1[i] = w1[i];
    for (int i = threadIdx.x; i < CDIM; i += blockDim.x) { sb1[i] = b1[i]; s2[i] = w2[i]; }
    if (threadIdx.x == 0) sb2 = b2[0];
    __syncthreads();
    int n = blockIdx.x * blockDim.x + threadIdx.x;
    if (n >= N_NODES) return;
    float a[CDIM];
    #pragma unroll
    for (int j = 0; j < CDIM; j++) a[j] = sb1[j];
    for (int k = 0; k < HDIM; k++) {
        float xv = HT[(size_t)k * N_NODES + n];
        const float* wr = s1 + k * CDIM;
        #pragma unroll
        for (int j = 0; j < CDIM; j++) a[j] = fmaf(xv, wr[j], a[j]);
    }
    float r = sb2;
    #pragma unroll
    for (int j = 0; j < CDIM; j++) r = fmaf(fmaxf(a[j], 0.0f), s2[j], r);
    out[n] = r;
}

// ---------------- host orchestration --------------------------------------------
extern "C" void kernel_launch(void* const* d_in, const int* in_sizes, int n_in,
                              void* d_out, int out_size) {
    const float* features = (const float*)d_in[0];
    const void*  e_row    = d_in[1];
    const void*  e_col    = d_in[2];
    const float* init_w   = (const float*)d_in[3];
    const float* init_b   = (const float*)d_in[4];
    const float* fm_w1 = (const float*)d_in[5],  *fm_b1 = (const float*)d_in[6];
    const float* fm_w2 = (const float*)d_in[7],  *fm_b2 = (const float*)d_in[8];
    const float* bm_w1 = (const float*)d_in[9],  *bm_b1 = (const float*)d_in[10];
    const float* bm_w2 = (const float*)d_in[11], *bm_b2 = (const float*)d_in[12];
    const float* fg_wih = (const float*)d_in[13], *fg_whh = (const float*)d_in[14];
    const float* fg_bih = (const float*)d_in[15], *fg_bhh = (const float*)d_in[16];
    const float* bg_wih = (const float*)d_in[17], *bg_whh = (const float*)d_in[18];
    const float* bg_bih = (const float*)d_in[19], *bg_bhh = (const float*)d_in[20];
    const float* cl_w1 = (const float*)d_in[21], *cl_b1 = (const float*)d_in[22];
    const float* cl_w2 = (const float*)d_in[23], *cl_b2 = (const float*)d_in[24];
    float* out = (float*)d_out;

    float *h, *h2, *m, *msg, *gi;
    int *row_i, *col_i, *degF, *degB, *rptrF, *rptrB, *curF, *curB, *csrF, *csrB, *incl, *bsums;
    uint32_t* wbia;
    cudaGetSymbolAddress((void**)&h,     g_h);
    cudaGetSymbolAddress((void**)&h2,    g_h2);
    cudaGetSymbolAddress((void**)&m,     g_m);
    cudaGetSymbolAddress((void**)&msg,   g_msg);
    cudaGetSymbolAddress((void**)&gi,    g_gi);
    cudaGetSymbolAddress((void**)&wbia,  g_wbia);
    cudaGetSymbolAddress((void**)&row_i, g_row);
    cudaGetSymbolAddress((void**)&col_i, g_col);
    cudaGetSymbolAddress((void**)&degF,  g_degF);
    cudaGetSymbolAddress((void**)&degB,  g_degB);
    cudaGetSymbolAddress((void**)&rptrF, g_rptrF);
    cudaGetSymbolAddress((void**)&rptrB, g_rptrB);
    cudaGetSymbolAddress((void**)&curF,  g_curF);
    cudaGetSymbolAddress((void**)&curB,  g_curB);
    cudaGetSymbolAddress((void**)&csrF,  g_csrF);
    cudaGetSymbolAddress((void**)&csrB,  g_csrB);
    cudaGetSymbolAddress((void**)&incl,  g_incl);
    cudaGetSymbolAddress((void**)&bsums, g_bsums);

    uint32_t* wbia_f = wbia;
    uint32_t* wbia_b = wbia + 2 * BW;

    const size_t smem_mlp  = (size_t)(HDIM * SXS + 5000 + 5000 + 150) * sizeof(float);
    const size_t smem_gate = (size_t)(HDIM * SXS + 6000 + 300) * sizeof(float);
    cudaFuncSetAttribute(mlp_tiled,  cudaFuncAttributeMaxDynamicSharedMemorySize, (int)smem_mlp);
    cudaFuncSetAttribute(gate_tiled, cudaFuncAttributeMaxDynamicSharedMemorySize, (int)smem_gate);
    cudaFuncSetAttribute(gi_mma,     cudaFuncAttributeMaxDynamicSharedMemorySize, GI_SMEM);

    const int GT    = N_NODES / MTILE;   // 3125
    const int GN256 = (N_NODES + 255) / 256;
    const int GE    = (N_EDGES + 255) / 256;
    const int GW    = (int)(((long long)N_NODES * 32 + 255) / 256);
    const int NB    = (N_NODES + 1023) / 1024;
    const int GP    = (BW + 255) / 256;

    // ---- preprocessing ----
    detect_kernel<<<1, 32>>>((const unsigned int*)e_row);
    convert_kernel<<<GE, 256>>>(e_row, e_col, row_i, col_i);
    cudaMemsetAsync(degF, 0, N_NODES * sizeof(int));
    cudaMemsetAsync(degB, 0, N_NODES * sizeof(int));
    deg_kernel<<<GE, 256>>>(row_i, col_i, degF, degB);
    scan_block<<<NB, 1024>>>(degF, incl, bsums, N_NODES);
    scan_sums<<<1, 32>>>(bsums, NB);
    scan_final<<<(N_NODES + 256) / 256, 256>>>(incl, degF, bsums, rptrF, N_NODES);
    scan_block<<<NB, 1024>>>(degB, incl, bsums, N_NODES);
    scan_sums<<<1, 32>>>(bsums, NB);
    scan_final<<<(N_NODES + 256) / 256, 256>>>(incl, degB, bsums, rptrB, N_NODES);
    cudaMemcpyAsync(curF, rptrF, N_NODES * sizeof(int), cudaMemcpyDeviceToDevice);
    cudaMemcpyAsync(curB, rptrB, N_NODES * sizeof(int), cudaMemcpyDeviceToDevice);
    scatter_kernel<<<GE, 256>>>(row_i, col_i, curF, curB, csrF, csrB);

    prep_wb<<<GP, 256>>>(fg_wih, wbia_f);
    prep_wb<<<GP, 256>>>(bg_wih, wbia_b);

    initT_kernel<<<GT, MTILE>>>(features, init_w, init_b, h);

    float* hc = h;
    float* hn = h2;

    for (int rnd = 0; rnd < 20; rnd++) {
        // forward pass
        mlp_tiled<<<GT, GTB, smem_mlp>>>(hc, fm_w1, fm_b1, fm_w2, fm_b2, m);
        spmm_gather<<<GW, 256>>>(rptrF, csrF, m, msg);
        gi_mma<<<GT, 256, GI_SMEM>>>(msg, wbia_f, fg_bih, gi);
        gate_tiled<<<GT, GTB, smem_gate>>>(gi, hc, fg_whh, fg_bhh, hn);
        { float* t = hc; hc = hn; hn = t; }
        // backward pass
        mlp_tiled<<<GT, GTB, smem_mlp>>>(hc, bm_w1, bm_b1, bm_w2, bm_b2, m);
        spmm_gather<<<GW, 256>>>(rptrB, csrB, m, msg);
        gi_mma<<<GT, 256, GI_SMEM>>>(msg, wbia_b, bg_bih, gi);
        gate_tiled<<<GT, GTB, smem_gate>>>(gi, hc, bg_whh, bg_bhh, hn);
        { float* t = hc; hc = hn; hn = t; }
    }

    classify_kernel<<<GN256, 256>>>(hc, cl_w1, cl_b1, cl_w2, cl_b2, out);
}

// round 12
// speedup vs baseline: 1.0962x; 1.0088x over previous
#include <cuda_runtime.h>
#include <cuda_bf16.h>
#include <cstdint>

#define N_NODES 400000
#define N_EDGES 1600000
#define HDIM 100
#define HDIM3 300
#define ADIM 50
#define CDIM 30
#define GTB 320          // threads for scalar tiled GEMM kernels
#define MTILE 128        // rows per CTA (400000 = 128 * 3125 exactly)
#define SXS 132          // k-major tile row stride

// ---- mma.sync gi GEMM geometry ----
#define BW 17472                 // 56*312 words per B split
#define AW 7680                  // 128*60 words per A split
#define A_OFF (2*BW)             // A base word offset in smem
#define GI_SMEM ((2*BW + 2*AW) * 4)   // 201216 bytes

typedef unsigned long long u64;

// ---------------- scratch (device globals) -------------------------------------
__device__ __align__(16) float g_h  [N_NODES * HDIM];
__device__ __align__(16) float g_h2 [N_NODES * HDIM];
__device__ __align__(16) float g_m  [N_NODES * HDIM];
__device__ __align__(16) float g_msg[N_NODES * HDIM];
__device__ __align__(16) float g_gi [(size_t)N_NODES * HDIM3];
__device__ __align__(16) uint32_t g_wbia[2][2 * BW];   // fwd/bwd wih bf16-split images
__device__ int g_row[N_EDGES];
__device__ int g_col[N_EDGES];
__device__ int g_is64;
__device__ int g_degF[N_NODES];
__device__ int g_degB[N_NODES];
__device__ int g_rptrF[N_NODES + 1];
__device__ int g_rptrB[N_NODES + 1];
__device__ int g_curF[N_NODES];
__device__ int g_curB[N_NODES];
__device__ int g_csrF[N_EDGES];
__device__ int g_csrB[N_EDGES];
__device__ int g_incl[N_NODES];
__device__ int g_bsums[512];

// ---------------- helpers --------------------------------------------------------
__device__ __forceinline__ u64 pack2(float x, float y) {
    u64 r; asm("mov.b64 %0, {%1, %2};" : "=l"(r) : "f"(x), "f"(y)); return r;
}
__device__ __forceinline__ float2 unpack2(u64 v) {
    float2 r; asm("mov.b64 {%0, %1}, %2;" : "=f"(r.x), "=f"(r.y) : "l"(v)); return r;
}
__device__ __forceinline__ void fma2(u64& d, u64 a, u64 b) {
    asm("fma.rn.f32x2 %0, %1, %2, %0;" : "+l"(d) : "l"(a), "l"(b));
}
__device__ __forceinline__ float ex2a(float x) {
    float r; asm("ex2.approx.f32 %0, %1;" : "=f"(r) : "f"(x)); return r;
}
__device__ __forceinline__ float rcpa(float x) {
    float r; asm("rcp.approx.f32 %0, %1;" : "=f"(r) : "f"(x)); return r;
}
__device__ __forceinline__ float fsigmoid(float x) {
    return rcpa(1.0f + ex2a(-1.4426950408889634f * x));
}
__device__ __forceinline__ float ftanh_(float x) {
    float e = ex2a(2.8853900817779268f * x);
    return fmaf(-2.0f, rcpa(e + 1.0f), 1.0f);
}
__device__ __forceinline__ unsigned short bfu(float x) {
    __nv_bfloat16 b = __float2bfloat16(x);
    return *reinterpret_cast<unsigned short*>(&b);
}
__device__ __forceinline__ float bff(float x) {
    return __bfloat162float(__float2bfloat16(x));
}
__device__ __forceinline__ void mma_bf16(float c[4],
    uint32_t a0, uint32_t a1, uint32_t a2, uint32_t a3,
    uint32_t b0, uint32_t b1) {
    asm volatile(
        "mma.sync.aligned.m16n8k16.row.col.f32.bf16.bf16.f32 "
        "{%0,%1,%2,%3}, {%4,%5,%6,%7}, {%8,%9}, {%0,%1,%2,%3};"
        : "+f"(c[0]), "+f"(c[1]), "+f"(c[2]), "+f"(c[3])
        : "r"(a0), "r"(a1), "r"(a2), "r"(a3), "r"(b0), "r"(b1));
}

// ---------------- edge dtype detection & normalization -------------------------
__global__ void detect_kernel(const unsigned int* __restrict__ w) {
    unsigned int v = w[2 * threadIdx.x + 1];
    unsigned int any = __ballot_sync(0xffffffffu, v != 0u);
    if (threadIdx.x == 0) g_is64 = (any == 0u) ? 1 : 0;
}

__global__ void convert_kernel(const void* __restrict__ rp, const void* __restrict__ cp,
                               int* __restrict__ ro, int* __restrict__ co) {
    int e = blockIdx.x * blockDim.x + threadIdx.x;
    if (e >= N_EDGES) return;
    if (g_is64) {
        ro[e] = (int)((const long long*)rp)[e];
        co[e] = (int)((const long long*)cp)[e];
    } else {
        ro[e] = ((const int*)rp)[e];
        co[e] = ((const int*)cp)[e];
    }
}

// ---------------- CSR build ------------------------------------------------------
__global__ void deg_kernel(const int* __restrict__ row, const int* __restrict__ col,
                           int* __restrict__ degF, int* __restrict__ degB) {
    int e = blockIdx.x * blockDim.x + threadIdx.x;
    if (e >= N_EDGES) return;
    atomicAdd(&degF[row[e]], 1);
    atomicAdd(&degB[col[e]], 1);
}

__global__ void scan_block(const int* __restrict__ deg, int* __restrict__ incl,
                           int* __restrict__ bsums, int n) {
    __shared__ int s[1024];
    int i = blockIdx.x * 1024 + threadIdx.x;
    int v = (i < n) ? deg[i] : 0;
    s[threadIdx.x] = v;
    __syncthreads();
    #pragma unroll
    for (int off = 1; off < 1024; off <<= 1) {
        int t = (threadIdx.x >= off) ? s[threadIdx.x - off] : 0;
        __syncthreads();
        s[threadIdx.x] += t;
        __syncthreads();
    }
    if (i < n) incl[i] = s[threadIdx.x];
    if (threadIdx.x == 1023) bsums[blockIdx.x] = s[1023];
}

__global__ void scan_sums(int* __restrict__ bsums, int nb) {
    if (threadIdx.x == 0) {
        int acc = 0;
        for (int b = 0; b < nb; b++) { int t = bsums[b]; bsums[b] = acc; acc += t; }
    }
}

__global__ void scan_final(const int* __restrict__ incl, const int* __restrict__ deg,
                           const int* __restrict__ bsums, int* __restrict__ rptr, int n) {
    int i = blockIdx.x * 256 + threadIdx.x;
    if (i < n) rptr[i] = incl[i] - deg[i] + bsums[i >> 10];
    if (i == n) rptr[n] = N_EDGES;
}

__global__ void scatter_kernel(const int* __restrict__ row, const int* __restrict__ col,
                               int* __restrict__ curF, int* __restrict__ curB,
                               int* __restrict__ csrF, int* __restrict__ csrB) {
    int e = blockIdx.x * blockDim.x + threadIdx.x;
    if (e >= N_EDGES) return;
    int r = row[e], c = col[e];
    int pF = atomicAdd(&curF[r], 1);
    csrF[pF] = c;
    int pB = atomicAdd(&curB[c], 1);
    csrB[pB] = r;
}

// ---------------- weight prep: Wih[100][300] -> 2 bf16-split pair images --------
__global__ void prep_wb(const float* __restrict__ W, uint32_t* __restrict__ o) {
    int e = blockIdx.x * 256 + threadIdx.x;
    if (e >= BW) return;
    int kq = e / 312, n = e - kq * 312;
    int k0 = 2 * kq, k1 = k0 + 1;
    float w0 = (k0 < 100 && n < 300) ? W[k0 * 300 + n] : 0.0f;
    float w1 = (k1 < 100 && n < 300) ? W[k1 * 300 + n] : 0.0f;
    o[e] = (uint32_t)bfu(w0) | ((uint32_t)bfu(w1) << 16);
    float r0 = w0 - bff(w0), r1 = w1 - bff(w1);
    o[BW + e] = (uint32_t)bfu(r0) | ((uint32_t)bfu(r1) << 16);
}

// ---------------- h0_T[d][n] = (features @ init_w + init_b)^T ------------------
__global__ void initT_kernel(const float* __restrict__ f, const float* __restrict__ w,
                             const float* __restrict__ b, float* __restrict__ hT) {
    __shared__ float sw[4 * HDIM];
    __shared__ float sb[HDIM];
    for (int i = threadIdx.x; i < 4 * HDIM; i += blockDim.x) sw[i] = w[i];
    for (int i = threadIdx.x; i < HDIM; i += blockDim.x) sb[i] = b[i];
    __syncthreads();
    int n = blockIdx.x * blockDim.x + threadIdx.x;
    float4 fv = *(const float4*)(f + (size_t)n * 4);
    #pragma unroll 4
    for (int d = 0; d < HDIM; d++) {
        float v = sb[d] + fv.x * sw[d] + fv.y * sw[HDIM + d]
                        + fv.z * sw[2 * HDIM + d] + fv.w * sw[3 * HDIM + d];
        hT[(size_t)d * N_NODES + n] = v;
    }
}

// ---------------- scalar tiled MLP (layer1 packed f32x2) ------------------------
__global__ void __launch_bounds__(GTB, 2) mlp_tiled(
    const float* __restrict__ HT,
    const float* __restrict__ w1, const float* __restrict__ b1,
    const float* __restrict__ w2, const float* __restrict__ b2,
    float* __restrict__ Mout) {
    extern __shared__ float sm[];
    float* sxT = sm;
    float* sw1 = sm + HDIM * SXS;
    float* sw2 = sw1 + 5000;
    float* sb  = sw2 + 5000;
    int base = blockIdx.x * MTILE;
    int lane = threadIdx.x & 31, wid = threadIdx.x >> 5;

    for (int i = threadIdx.x; i < 5000; i += GTB) { sw1[i] = w1[i]; sw2[i] = w2[i]; }
    if (threadIdx.x < 50) sb[threadIdx.x] = b1[threadIdx.x];
    else if (threadIdx.x < 150) sb[threadIdx.x] = b2[threadIdx.x - 50];
    for (int idx = threadIdx.x; idx < HDIM * 32; idx += GTB) {
        int k = idx >> 5, rq = idx & 31;
        *(float4*)(sxT + k * SXS + rq * 4) =
            *(const float4*)(HT + (size_t)k * N_NODES + base + rq * 4);
    }
    __syncthreads();

    u64 a01[5], a23[5];
    #pragma unroll
    for (int j = 0; j < 5; j++) {
        float b = sb[wid * 5 + j];
        u64 bb = pack2(b, b);
        a01[j] = bb; a23[j] = bb;
    }
    const float* xp = sxT + lane * 4;
    for (int k = 0; k < HDIM; k++) {
        float4 a = *(const float4*)(xp + k * SXS);
        u64 axy = pack2(a.x, a.y), azw = pack2(a.z, a.w);
        const float* wr = sw1 + k * ADIM + wid * 5;
        #pragma unroll
        for (int j = 0; j < 5; j++) {
            float wv = wr[j];
            u64 w2 = pack2(wv, wv);
            fma2(a01[j], axy, w2);
            fma2(a23[j], azw, w2);
        }
    }
    __syncthreads();
    #pragma unroll
    for (int j = 0; j < 5; j++) {
        float2 v01 = unpack2(a01[j]);
        float2 v23 = unpack2(a23[j]);
        float* dst = sxT + (wid * 5 + j) * SXS + lane * 4;
        dst[0] = fmaxf(v01.x, 0.0f);
        dst[1] = fmaxf(v01.y, 0.0f);
        dst[2] = fmaxf(v23.x, 0.0f);
        dst[3] = fmaxf(v23.y, 0.0f);
    }
    __syncthreads();

    u64 acc[20];
    const u64* bb = (const u64*)(sb + 50 + wid * 10);
    #pragma unroll
    for (int r = 0; r < 4; r++)
        #pragma unroll
        for (int j = 0; j < 5; j++) acc[r * 5 + j] = bb[j];
    for (int k = 0; k < ADIM; k++) {
        float4 a = *(const float4*)(xp + k * SXS);
        u64 a0 = pack2(a.x, a.x), a1p = pack2(a.y, a.y);
        u64 a2 = pack2(a.z, a.z), a3 = pack2(a.w, a.w);
        const float* wr = sw2 + k * HDIM + wid * 10;
        #pragma unroll
        for (int j = 0; j < 5; j++) {
            u64 wv = *(const u64*)(wr + 2 * j);
            fma2(acc[j],      a0,  wv);
            fma2(acc[5 + j],  a1p, wv);
            fma2(acc[10 + j], a2,  wv);
            fma2(acc[15 + j], a3,  wv);
        }
    }
    __syncthreads();
    #pragma unroll
    for (int j = 0; j < 5; j++) {
        int c = wid * 10 + 2 * j;
        #pragma unroll
        for (int r = 0; r < 4; r++) {
            float2 v = unpack2(acc[r * 5 + j]);
            sxT[c * SXS + lane * 4 + r]       = v.x;
            sxT[(c + 1) * SXS + lane * 4 + r] = v.y;
        }
    }
    __syncthreads();
    for (int idx = threadIdx.x; idx < 25 * MTILE; idx += GTB) {
        int row = idx & 127, c4 = (idx >> 7) * 4;
        float4 v = make_float4(sxT[c4 * SXS + row], sxT[(c4 + 1) * SXS + row],
                               sxT[(c4 + 2) * SXS + row], sxT[(c4 + 3) * SXS + row]);
        *(float4*)(Mout + (size_t)(base + row) * HDIM + c4) = v;
    }
}

// ---------------- warp-per-node CSR gather (index prefetch + 2x unroll) ----------
__global__ void __launch_bounds__(256) spmm_gather(
    const int* __restrict__ rptr, const int* __restrict__ csr,
    const float* __restrict__ m, float* __restrict__ msg) {
    int warp = (blockIdx.x * blockDim.x + threadIdx.x) >> 5;
    int lane = threadIdx.x & 31;
    if (warp >= N_NODES) return;
    int p0 = rptr[warp], p1 = rptr[warp + 1];
    int deg = p1 - p0;
    // prefetch up to 32 neighbor indices in one coalesced load
    int pre = (lane < deg) ? csr[p0 + lane] : 0;
    float4 acc0 = make_float4(0.f, 0.f, 0.f, 0.f);
    float4 acc1 = make_float4(0.f, 0.f, 0.f, 0.f);
    int nd = min(deg, 32);
    int j = 0;
    for (; j + 1 < nd; j += 2) {
        int s0 = __shfl_sync(0xffffffffu, pre, j);
        int s1 = __shfl_sync(0xffffffffu, pre, j + 1);
        if (lane < 25) {
            float4 v0 = *(const float4*)(m + (size_t)s0 * HDIM + lane * 4);
            float4 v1 = *(const float4*)(m + (size_t)s1 * HDIM + lane * 4);
            acc0.x += v0.x; acc0.y += v0.y; acc0.z += v0.z; acc0.w += v0.w;
            acc1.x += v1.x; acc1.y += v1.y; acc1.z += v1.z; acc1.w += v1.w;
        }
    }
    if (j < nd) {
        int s0 = __shfl_sync(0xffffffffu, pre, j);
        if (lane < 25) {
            float4 v0 = *(const float4*)(m + (size_t)s0 * HDIM + lane * 4);
            acc0.x += v0.x; acc0.y += v0.y; acc0.z += v0.z; acc0.w += v0.w;
        }
    }
    // rare tail (deg > 32)
    for (int p = p0 + 32; p < p1; p++) {
        int s = csr[p];
        if (lane < 25) {
            float4 v = *(const float4*)(m + (size_t)s * HDIM + lane * 4);
            acc0.x += v.x; acc0.y += v.y; acc0.z += v.z; acc0.w += v.w;
        }
    }
    if (lane < 25) {
        acc0.x += acc1.x; acc0.y += acc1.y; acc0.z += acc1.z; acc0.w += acc1.w;
        *(float4*)(msg + (size_t)warp * HDIM + lane * 4) = acc0;
    }
}

// ---------------- gi via mma.sync: giT = (msg @ Wih + bih)^T --------------------
template<int NT0, int NT>
__device__ __forceinline__ void gi_compute_half(
    const uint32_t* __restrict__ smu, float* __restrict__ outT,
    const float* __restrict__ Bih, int base, int w, int lane) {
    int q = lane & 3, l4 = lane >> 2;
    int r = w * 16 + l4;
    const uint32_t* A0 = smu + A_OFF + r * 60;
    float c[NT][4];
    #pragma unroll
    for (int t = 0; t < NT; t++) { c[t][0] = c[t][1] = c[t][2] = c[t][3] = 0.0f; }
    #pragma unroll
    for (int ks = 0; ks < 7; ks++) {
        uint32_t a00 = A0[ks * 8 + q],            a01 = A0[480 + ks * 8 + q];
        uint32_t a02 = A0[ks * 8 + 4 + q],        a03 = A0[480 + ks * 8 + 4 + q];
        uint32_t a10 = A0[AW + ks * 8 + q],       a11 = A0[AW + 480 + ks * 8 + q];
        uint32_t a12 = A0[AW + ks * 8 + 4 + q],   a13 = A0[AW + 480 + ks * 8 + 4 + q];
        const uint32_t* B0 = smu + (ks * 8 + q) * 312;
        const uint32_t* B1 = smu + (ks * 8 + 4 + q) * 312;
        #pragma unroll
        for (int t = 0; t < NT; t++) {
            int nb = (NT0 + t) * 8 + l4;
            uint32_t b00 = B0[nb],       b01 = B1[nb];
            uint32_t b10 = B0[BW + nb],  b11 = B1[BW + nb];
            mma_bf16(c[t], a00, a01, a02, a03, b00, b01);   // aHi * bHi
            mma_bf16(c[t], a10, a11, a12, a13, b00, b01);   // aLo * bHi
            mma_bf16(c[t], a00, a01, a02, a03, b10, b11);   // aHi * bLo
        }
    }
    int node = base + r;
    #pragma unroll
    for (int t = 0; t < NT; t++) {
        int n0 = (NT0 + t) * 8 + q * 2;
        if (n0 < 300) {
            float bia = Bih[n0];
            outT[(size_t)n0 * N_NODES + node]     = c[t][0] + bia;
            outT[(size_t)n0 * N_NODES + node + 8] = c[t][2] + bia;
        }
        if (n0 + 1 < 300) {
            float bib = Bih[n0 + 1];
            outT[(size_t)(n0 + 1) * N_NODES + node]     = c[t][1] + bib;
            outT[(size_t)(n0 + 1) * N_NODES + node + 8] = c[t][3] + bib;
        }
    }
}

__global__ void __launch_bounds__(256, 1) gi_mma(
    const float* __restrict__ MSG, const uint32_t* __restrict__ GB,
    const float* __restrict__ Bih, float* __restrict__ outT) {
    extern __shared__ __align__(16) uint32_t smu[];
    int tid = threadIdx.x;
    int base = blockIdx.x * MTILE;
    {
        const uint4* src = (const uint4*)GB;
        uint4* dst = (uint4*)smu;
        for (int i = tid; i < (2 * BW) / 4; i += 256) dst[i] = src[i];
    }
    for (int idx = tid; idx < 128 * 56; idx += 256) {
        int row = idx / 56;
        int kq = idx - row * 56;
        float2 v = make_float2(0.0f, 0.0f);
        if (kq < 50) v = *(const float2*)(MSG + (size_t)(base + row) * HDIM + 2 * kq);
        uint32_t hi = (uint32_t)bfu(v.x) | ((uint32_t)bfu(v.y) << 16);
        float rx = v.x - bff(v.x), ry = v.y - bff(v.y);
        uint32_t lo = (uint32_t)bfu(rx) | ((uint32_t)bfu(ry) << 16);
        smu[A_OFF + row * 60 + kq]      = hi;
        smu[A_OFF + AW + row * 60 + kq] = lo;
    }
    __syncthreads();
    int w = tid >> 5, lane = tid & 31;
    gi_compute_half<0, 19>(smu, outT, Bih, base, w, lane);
    gi_compute_half<19, 20>(smu, outT, Bih, base, w, lane);
}

// ---------------- tiled gate: h' = GRU(giT, hT) (scalar, fast activations) ------
__global__ void __launch_bounds__(GTB, 2) gate_tiled(
    const float* __restrict__ GIT,
    const float* __restrict__ HT,
    const float* __restrict__ W, const float* __restrict__ B,
    float* __restrict__ HoutT) {
    extern __shared__ float sm[];
    float* sxT = sm;
    float* sw  = sm + HDIM * SXS;
    float* sb  = sw + 6000;
    int base = blockIdx.x * MTILE;
    int lane = threadIdx.x & 31, wid = threadIdx.x >> 5;
    for (int i = threadIdx.x; i < HDIM3; i += GTB) sb[i] = B[i];
    for (int idx = threadIdx.x; idx < HDIM * 32; idx += GTB) {
        int k = idx >> 5, rq = idx & 31;
        *(float4*)(sxT + k * SXS + rq * 4) =
            *(const float4*)(HT + (size_t)k * N_NODES + base + rq * 4);
    }
    const float* xp = sxT + lane * 4;
    size_t rowoff = base + lane * 4;
    for (int ch = 0; ch < 5; ch++) {
        int d0 = ch * 20;
        __syncthreads();
        for (int i = threadIdx.x * 4; i < 6000; i += GTB * 4) {
            int k = i / 60, rem = i - k * 60;
            int g = rem / 20, j = rem - g * 20;
            *(float4*)(sw + i) = *(const float4*)(W + (size_t)k * HDIM3 + g * HDIM + d0 + j);
        }
        __syncthreads();
        int cl = wid * 2;
        u64 ar[4], az[4], an[4];
        {
            u64 br = *(const u64*)(sb + d0 + cl);
            u64 bz = *(const u64*)(sb + HDIM + d0 + cl);
            u64 bn = *(const u64*)(sb + 2 * HDIM + d0 + cl);
            #pragma unroll
            for (int r = 0; r < 4; r++) { ar[r] = br; az[r] = bz; an[r] = bn; }
        }
        for (int k = 0; k < HDIM; k++) {
            float4 a = *(const float4*)(xp + k * SXS);
            u64 a0 = pack2(a.x, a.x), a1p = pack2(a.y, a.y);
            u64 a2 = pack2(a.z, a.z), a3 = pack2(a.w, a.w);
            const float* wr = sw + k * 60 + cl;
            u64 wrv = *(const u64*)(wr);
            u64 wzv = *(const u64*)(wr + 20);
            u64 wnv = *(const u64*)(wr + 40);
            fma2(ar[0], a0, wrv); fma2(ar[1], a1p, wrv);
            fma2(ar[2], a2, wrv); fma2(ar[3], a3, wrv);
            fma2(az[0], a0, wzv); fma2(az[1], a1p, wzv);
            fma2(az[2], a2, wzv); fma2(az[3], a3, wzv);
            fma2(an[0], a0, wnv); fma2(an[1], a1p, wnv);
            fma2(an[2], a2, wnv); fma2(an[3], a3, wnv);
        }
        int c = d0 + cl;
        float4 gr0 = *(const float4*)(GIT + (size_t)c * N_NODES + rowoff);
        float4 gr1 = *(const float4*)(GIT + (size_t)(c + 1) * N_NODES + rowoff);
        float4 gz0 = *(const float4*)(GIT + (size_t)(HDIM + c) * N_NODES + rowoff);
        float4 gz1 = *(const float4*)(GIT + (size_t)(HDIM + c + 1) * N_NODES + rowoff);
        float4 gn0 = *(const float4*)(GIT + (size_t)(2 * HDIM + c) * N_NODES + rowoff);
        float4 gn1 = *(const float4*)(GIT + (size_t)(2 * HDIM + c + 1) * N_NODES + rowoff);
        float4 h0 = *(const float4*)(sxT + c * SXS + lane * 4);
        float4 h1 = *(const float4*)(sxT + (c + 1) * SXS + lane * 4);
        float4 o0, o1;
        {
            const float* grp0 = &gr0.x; const float* grp1 = &gr1.x;
            const float* gzp0 = &gz0.x; const float* gzp1 = &gz1.x;
            const float* gnp0 = &gn0.x; const float* gnp1 = &gn1.x;
            const float* hp0 = &h0.x;  const float* hp1 = &h1.x;
            float* op0 = &o0.x; float* op1 = &o1.x;
            #pragma unroll
            for (int r = 0; r < 4; r++) {
                float2 hr = unpack2(ar[r]);
                float2 hz = unpack2(az[r]);
                float2 hn = unpack2(an[r]);
                float r0 = fsigmoid(grp0[r] + hr.x);
                float r1 = fsigmoid(grp1[r] + hr.y);
                float z0 = fsigmoid(gzp0[r] + hz.x);
                float z1 = fsigmoid(gzp1[r] + hz.y);
                float n0 = ftanh_(gnp0[r] + r0 * hn.x);
                float n1 = ftanh_(gnp1[r] + r1 * hn.y);
                op0[r] = (1.0f - z0) * n0 + z0 * hp0[r];
                op1[r] = (1.0f - z1) * n1 + z1 * hp1[r];
            }
        }
        *(float4*)(HoutT + (size_t)c * N_NODES + rowoff) = o0;
        *(float4*)(HoutT + (size_t)(c + 1) * N_NODES + rowoff) = o1;
    }
}

// ---------------- classifier from transposed h ----------------------------------
__global__ void __launch_bounds__(256) classify_kernel(
    const float* __restrict__ HT,
    const float* __restrict__ w1, const float* __restrict__ b1,
    const float* __restrict__ w2, const float* __restrict__ b2,
    float* __restrict__ out) {
    __shared__ float s1[HDIM * CDIM];
    __shared__ float sb1[CDIM];
    __shared__ float s2[CDIM];
    __shared__ float sb2;
    for (int i = threadIdx.x; i < HDIM * CDIM; i += blockDim.x) s1[i] = w1[i];
    for (int i = threadIdx.x; i < CDIM; i += blockDim.x) { sb1[i] = b1[i]; s2[i] = w2[i]; }
    if (threadIdx.x == 0) sb2 = b2[0];
    __syncthreads();
    int n = blockIdx.x * blockDim.x + threadIdx.x;
    if (n >= N_NODES) return;
    float a[CDIM];
    #pragma unroll
    for (int j = 0; j < CDIM; j++) a[j] = sb1[j];
    for (int k = 0; k < HDIM; k++) {
        float xv = HT[(size_t)k * N_NODES + n];
        const float* wr = s1 + k * CDIM;
        #pragma unroll
        for (int j = 0; j < CDIM; j++) a[j] = fmaf(xv, wr[j], a[j]);
    }
    float r = sb2;
    #pragma unroll
    for (int j = 0; j < CDIM; j++) r = fmaf(fmaxf(a[j], 0.0f), s2[j], r);
    out[n] = r;
}

// ---------------- host orchestration --------------------------------------------
extern "C" void kernel_launch(void* const* d_in, const int* in_sizes, int n_in,
                              void* d_out, int out_size) {
    const float* features = (const float*)d_in[0];
    const void*  e_row    = d_in[1];
    const void*  e_col    = d_in[2];
    const float* init_w   = (const float*)d_in[3];
    const float* init_b   = (const float*)d_in[4];
    const float* fm_w1 = (const float*)d_in[5],  *fm_b1 = (const float*)d_in[6];
    const float* fm_w2 = (const float*)d_in[7],  *fm_b2 = (const float*)d_in[8];
    const float* bm_w1 = (const float*)d_in[9],  *bm_b1 = (const float*)d_in[10];
    const float* bm_w2 = (const float*)d_in[11], *bm_b2 = (const float*)d_in[12];
    const float* fg_wih = (const float*)d_in[13], *fg_whh = (const float*)d_in[14];
    const float* fg_bih = (const float*)d_in[15], *fg_bhh = (const float*)d_in[16];
    const float* bg_wih = (const float*)d_in[17], *bg_whh = (const float*)d_in[18];
    const float* bg_bih = (const float*)d_in[19], *bg_bhh = (const float*)d_in[20];
    const float* cl_w1 = (const float*)d_in[21], *cl_b1 = (const float*)d_in[22];
    const float* cl_w2 = (const float*)d_in[23], *cl_b2 = (const float*)d_in[24];
    float* out = (float*)d_out;

    float *h, *h2, *m, *msg, *gi;
    int *row_i, *col_i, *degF, *degB, *rptrF, *rptrB, *curF, *curB, *csrF, *csrB, *incl, *bsums;
    uint32_t* wbia;
    cudaGetSymbolAddress((void**)&h,     g_h);
    cudaGetSymbolAddress((void**)&h2,    g_h2);
    cudaGetSymbolAddress((void**)&m,     g_m);
    cudaGetSymbolAddress((void**)&msg,   g_msg);
    cudaGetSymbolAddress((void**)&gi,    g_gi);
    cudaGetSymbolAddress((void**)&wbia,  g_wbia);
    cudaGetSymbolAddress((void**)&row_i, g_row);
    cudaGetSymbolAddress((void**)&col_i, g_col);
    cudaGetSymbolAddress((void**)&degF,  g_degF);
    cudaGetSymbolAddress((void**)&degB,  g_degB);
    cudaGetSymbolAddress((void**)&rptrF, g_rptrF);
    cudaGetSymbolAddress((void**)&rptrB, g_rptrB);
    cudaGetSymbolAddress((void**)&curF,  g_curF);
    cudaGetSymbolAddress((void**)&curB,  g_curB);
    cudaGetSymbolAddress((void**)&csrF,  g_csrF);
    cudaGetSymbolAddress((void**)&csrB,  g_csrB);
    cudaGetSymbolAddress((void**)&incl,  g_incl);
    cudaGetSymbolAddress((void**)&bsums, g_bsums);

    uint32_t* wbia_f = wbia;
    uint32_t* wbia_b = wbia + 2 * BW;

    const size_t smem_mlp  = (size_t)(HDIM * SXS + 5000 + 5000 + 150) * sizeof(float);
    const size_t smem_gate = (size_t)(HDIM * SXS + 6000 + 300) * sizeof(float);
    cudaFuncSetAttribute(mlp_tiled,  cudaFuncAttributeMaxDynamicSharedMemorySize, (int)smem_mlp);
    cudaFuncSetAttribute(gate_tiled, cudaFuncAttributeMaxDynamicSharedMemorySize, (int)smem_gate);
    cudaFuncSetAttribute(gi_mma,     cudaFuncAttributeMaxDynamicSharedMemorySize, GI_SMEM);

    const int GT    = N_NODES / MTILE;   // 3125
    const int GN256 = (N_NODES + 255) / 256;
    const int GE    = (N_EDGES + 255) / 256;
    const int GW    = (int)(((long long)N_NODES * 32 + 255) / 256);
    const int NB    = (N_NODES + 1023) / 1024;
    const int GP    = (BW + 255) / 256;

    // ---- preprocessing ----
    detect_kernel<<<1, 32>>>((const unsigned int*)e_row);
    convert_kernel<<<GE, 256>>>(e_row, e_col, row_i, col_i);
    cudaMemsetAsync(degF, 0, N_NODES * sizeof(int));
    cudaMemsetAsync(degB, 0, N_NODES * sizeof(int));
    deg_kernel<<<GE, 256>>>(row_i, col_i, degF, degB);
    scan_block<<<NB, 1024>>>(degF, incl, bsums, N_NODES);
    scan_sums<<<1, 32>>>(bsums, NB);
    scan_final<<<(N_NODES + 256) / 256, 256>>>(incl, degF, bsums, rptrF, N_NODES);
    scan_block<<<NB, 1024>>>(degB, incl, bsums, N_NODES);
    scan_sums<<<1, 32>>>(bsums, NB);
    scan_final<<<(N_NODES + 256) / 256, 256>>>(incl, degB, bsums, rptrB, N_NODES);
    cudaMemcpyAsync(curF, rptrF, N_NODES * sizeof(int), cudaMemcpyDeviceToDevice);
    cudaMemcpyAsync(curB, rptrB, N_NODES * sizeof(int), cudaMemcpyDeviceToDevice);
    scatter_kernel<<<GE, 256>>>(row_i, col_i, curF, curB, csrF, csrB);

    prep_wb<<<GP, 256>>>(fg_wih, wbia_f);
    prep_wb<<<GP, 256>>>(bg_wih, wbia_b);

    initT_kernel<<<GT, MTILE>>>(features, init_w, init_b, h);

    float* hc = h;
    float* hn = h2;

    for (int rnd = 0; rnd < 20; rnd++) {
        // forward pass
        mlp_tiled<<<GT, GTB, smem_mlp>>>(hc, fm_w1, fm_b1, fm_w2, fm_b2, m);
        spmm_gather<<<GW, 256>>>(rptrF, csrF, m, msg);
        gi_mma<<<GT, 256, GI_SMEM>>>(msg, wbia_f, fg_bih, gi);
        gate_tiled<<<GT, GTB, smem_gate>>>(gi, hc, fg_whh, fg_bhh, hn);
        { float* t = hc; hc = hn; hn = t; }
        // backward pass
        mlp_tiled<<<GT, GTB, smem_mlp>>>(hc, bm_w1, bm_b1, bm_w2, bm_b2, m);
        spmm_gather<<<GW, 256>>>(rptrB, csrB, m, msg);
        gi_mma<<<GT, 256, GI_SMEM>>>(msg, wbia_b, bg_bih, gi);
        gate_tiled<<<GT, GTB, smem_gate>>>(gi, hc, bg_whh, bg_bhh, hn);
        { float* t = hc; hc = hn; hn = t; }
    }

    classify_kernel<<<GN256, 256>>>(hc, cl_w1, cl_b1, cl_w2, cl_b2, out);
}